// round 2
// baseline (speedup 1.0000x reference)
#include <cuda_runtime.h>
#include <math.h>

#define BSZ 2
#define SEQ 2048
#define DD 1024
#define CH 128
#define NCH 16
#define MTOT (BSZ*SEQ)        // 4096
#define EPSV 1e-6f

// ---------------- scratch (device globals; no allocation allowed) ----------------
__device__ float d_sq[MTOT*DD];                    // elu+1(q)
__device__ float d_sk[MTOT*DD];                    // elu+1(k)
__device__ float d_v [MTOT*DD];
__device__ float d_memout[MTOT*DD];
__device__ float d_local[MTOT*DD];
__device__ float d_G[(size_t)BSZ*NCH*DD*DD];       // per-chunk KV outer products -> exclusive prefix
__device__ float d_zz[BSZ*NCH*DD];                 // per-chunk k colsums -> exclusive prefix
__device__ float d_Abuf[BSZ*NCH*CH*CH];            // masked intra-chunk scores
__device__ float d_den[BSZ*NCH*CH];                // clipped denominators
__device__ float d_normq[MTOT];                    // clipped memory norms
__device__ float d_scal[2];                        // [0]=sigmoid(gate), [1]=active

// ---------------- small kernels ----------------
__global__ void scalars_kernel(const float* __restrict__ gate,
                               const float* __restrict__ mnorm) {
    __shared__ float sh[1024];
    int t = threadIdx.x;
    sh[t] = mnorm[t];
    __syncthreads();
    for (int s = 512; s > 0; s >>= 1) { if (t < s) sh[t] += sh[t+s]; __syncthreads(); }
    if (t == 0) {
        d_scal[0] = 1.f / (1.f + expf(-gate[0]));
        d_scal[1] = (sh[0] >= EPSV) ? 1.f : 0.f;
    }
}

// norm_q[row] = clip(dot(sq_row, memory_norm), EPS)   (warp per row)
__global__ void normq_kernel(const float* __restrict__ mnorm) {
    int warp = (blockIdx.x * blockDim.x + threadIdx.x) >> 5;
    int lane = threadIdx.x & 31;
    if (warp >= MTOT) return;
    const float* row = d_sq + (size_t)warp * DD;
    float s = 0.f;
    for (int k = lane; k < DD; k += 32) s += row[k] * mnorm[k];
    #pragma unroll
    for (int o = 16; o > 0; o >>= 1) s += __shfl_xor_sync(0xffffffffu, s, o);
    if (lane == 0) d_normq[warp] = fmaxf(s, EPSV);
}

// per-chunk colsum of sk -> d_zz[b,n,d]
__global__ void zc_kernel() {
    int idx = blockIdx.x * blockDim.x + threadIdx.x;   // over BSZ*NCH*DD = 32768
    if (idx >= BSZ*NCH*DD) return;
    int d = idx % DD; int bn = idx / DD;
    int b = bn >> 4, n = bn & 15;
    const float* base = d_sk + (size_t)(b*SEQ + n*CH)*DD + d;
    float s = 0.f;
    #pragma unroll 4
    for (int i = 0; i < CH; ++i) s += base[(size_t)i*DD];
    d_zz[idx] = s;
}

// exclusive prefix over chunks, in place
__global__ void zprefix_kernel() {
    int idx = blockIdx.x * blockDim.x + threadIdx.x;   // over BSZ*DD = 2048
    if (idx >= BSZ*DD) return;
    int b = idx / DD, d = idx % DD;
    float run = 0.f;
    for (int n = 0; n < NCH; ++n) {
        float* p = d_zz + (size_t)(b*NCH + n)*DD + d;
        float t = *p; *p = run; run += t;
    }
}

__global__ void gprefix_kernel() {
    size_t idx = (size_t)blockIdx.x * blockDim.x + threadIdx.x;  // over BSZ*DD*DD
    if (idx >= (size_t)BSZ*DD*DD) return;
    int b = (int)(idx / ((size_t)DD*DD));
    size_t rem = idx % ((size_t)DD*DD);
    float run = 0.f;
    for (int n = 0; n < NCH; ++n) {
        float* p = d_G + ((size_t)(b*NCH + n)*DD*DD) + rem;
        float t = *p; *p = run; run += t;
    }
}

// den[b,n,i] = clip(rowsum(A) + dot(sq_i, z_n), EPS)   (warp per row)
__global__ void den_kernel() {
    int warp = (blockIdx.x * blockDim.x + threadIdx.x) >> 5;
    int lane = threadIdx.x & 31;
    if (warp >= BSZ*NCH*CH) return;
    int bn = warp / CH, i = warp % CH;
    int b = bn >> 4, n = bn & 15;
    const float* qr = d_sq + (size_t)(b*SEQ + n*CH + i)*DD;
    const float* zr = d_zz + (size_t)bn*DD;
    float s = 0.f;
    for (int k = lane; k < DD; k += 32) s += qr[k] * zr[k];
    const float* ar = d_Abuf + (size_t)bn*CH*CH + (size_t)i*CH;
    for (int j = lane; j < CH; j += 32) s += ar[j];
    #pragma unroll
    for (int o = 16; o > 0; o >>= 1) s += __shfl_xor_sync(0xffffffffu, s, o);
    if (lane == 0) d_den[warp] = fmaxf(s, EPSV);
}

// ---------------- GEMM core (64x64x16 tile, 256 thr, 4x4 microtile) ----------------
__device__ __forceinline__ void mm_tile(const float (&As)[16][68], const float (&Bs)[16][68],
                                        float (&acc)[4][4], int tx, int ty) {
#pragma unroll
    for (int kk = 0; kk < 16; ++kk) {
        float4 a4 = *(const float4*)&As[kk][ty*4];
        float4 b4 = *(const float4*)&Bs[kk][tx*4];
        float av[4] = {a4.x, a4.y, a4.z, a4.w};
        float bv[4] = {b4.x, b4.y, b4.z, b4.w};
#pragma unroll
        for (int i = 0; i < 4; ++i)
#pragma unroll
            for (int j = 0; j < 4; ++j)
                acc[i][j] = fmaf(av[i], bv[j], acc[i][j]);
    }
}

// C = A @ B^T, A[M,K] rm, B[N,K] rm.  WHICH: 0->d_sq(elu) 1->d_sk(elu) 2->d_v
template<int WHICH>
__global__ void __launch_bounds__(256) gemm_proj(
    const float* __restrict__ A, const float* __restrict__ Bm, int M, int N, int K)
{
    __shared__ float As[16][68], Bs[16][68];
    const int tid = threadIdx.x;
    const int tx = tid & 15, ty = tid >> 4;
    const int lk = tid & 15, lm = tid >> 4;
    const int m0 = blockIdx.y * 64, n0 = blockIdx.x * 64;
    float acc[4][4] = {};
    for (int k0 = 0; k0 < K; k0 += 16) {
        #pragma unroll
        for (int r = 0; r < 4; ++r)
            As[lk][lm + 16*r] = A[(size_t)(m0 + lm + 16*r)*K + k0 + lk];
        #pragma unroll
        for (int r = 0; r < 4; ++r)
            Bs[lk][lm + 16*r] = Bm[(size_t)(n0 + lm + 16*r)*K + k0 + lk];
        __syncthreads();
        mm_tile(As, Bs, acc, tx, ty);
        __syncthreads();
    }
    float* C = (WHICH == 0) ? d_sq : (WHICH == 1) ? d_sk : d_v;
    #pragma unroll
    for (int i = 0; i < 4; ++i) {
        int m = m0 + ty*4 + i;
        #pragma unroll
        for (int j = 0; j < 4; ++j) {
            int n = n0 + tx*4 + j;
            float v = acc[i][j];
            if (WHICH < 2) v = (v > 0.f) ? v + 1.f : expf(v);  // elu(x)+1
            C[(size_t)m*N + n] = v;
        }
    }
}

// d_memout = active * (sq @ memory) / normq   (B [K,N] rm)
__global__ void __launch_bounds__(256) gemm_memout(const float* __restrict__ Bm)
{
    __shared__ float As[16][68], Bs[16][68];
    const int tid = threadIdx.x;
    const int tx = tid & 15, ty = tid >> 4;
    const int lk = tid & 15, lm = tid >> 4;
    const int ln = tid & 63, lk2 = tid >> 6;
    const int m0 = blockIdx.y * 64, n0 = blockIdx.x * 64;
    float acc[4][4] = {};
    for (int k0 = 0; k0 < DD; k0 += 16) {
        #pragma unroll
        for (int r = 0; r < 4; ++r)
            As[lk][lm + 16*r] = d_sq[(size_t)(m0 + lm + 16*r)*DD + k0 + lk];
        #pragma unroll
        for (int r = 0; r < 4; ++r)
            Bs[lk2 + 4*r][ln] = Bm[(size_t)(k0 + lk2 + 4*r)*DD + n0 + ln];
        __syncthreads();
        mm_tile(As, Bs, acc, tx, ty);
        __syncthreads();
    }
    float act = d_scal[1];
    #pragma unroll
    for (int i = 0; i < 4; ++i) {
        int m = m0 + ty*4 + i;
        float sc = act / d_normq[m];
        #pragma unroll
        for (int j = 0; j < 4; ++j)
            d_memout[(size_t)m*DD + n0 + tx*4 + j] = acc[i][j] * sc;
    }
}

// batched: G[bn] = sk_chunk^T @ v_chunk   ([D,D], K=CH)
__global__ void __launch_bounds__(256) gemm_kv()
{
    int bn = blockIdx.z; int b = bn >> 4, n = bn & 15;
    const float* Ak = d_sk + (size_t)(b*SEQ + n*CH)*DD;
    const float* Bv = d_v  + (size_t)(b*SEQ + n*CH)*DD;
    float* C = d_G + (size_t)bn*DD*DD;
    __shared__ float As[16][68], Bs[16][68];
    const int tid = threadIdx.x;
    const int tx = tid & 15, ty = tid >> 4;
    const int ln = tid & 63, lk2 = tid >> 6;
    const int m0 = blockIdx.y * 64, n0 = blockIdx.x * 64;
    float acc[4][4] = {};
    for (int k0 = 0; k0 < CH; k0 += 16) {
        #pragma unroll
        for (int r = 0; r < 4; ++r)
            As[lk2 + 4*r][ln] = Ak[(size_t)(k0 + lk2 + 4*r)*DD + m0 + ln];
        #pragma unroll
        for (int r = 0; r < 4; ++r)
            Bs[lk2 + 4*r][ln] = Bv[(size_t)(k0 + lk2 + 4*r)*DD + n0 + ln];
        __syncthreads();
        mm_tile(As, Bs, acc, tx, ty);
        __syncthreads();
    }
    #pragma unroll
    for (int i = 0; i < 4; ++i)
        #pragma unroll
        for (int j = 0; j < 4; ++j)
            C[(size_t)(m0 + ty*4 + i)*DD + n0 + tx*4 + j] = acc[i][j];
}

// batched: A[bn] = mask .* (sq_chunk @ sk_chunk^T)   ([128,128], K=D)
__global__ void __launch_bounds__(256) gemm_scores()
{
    int bn = blockIdx.z; int b = bn >> 4, n = bn & 15;
    const float* Aq = d_sq + (size_t)(b*SEQ + n*CH)*DD;
    const float* Bk = d_sk + (size_t)(b*SEQ + n*CH)*DD;
    float* C = d_Abuf + (size_t)bn*CH*CH;
    __shared__ float As[16][68], Bs[16][68];
    const int tid = threadIdx.x;
    const int tx = tid & 15, ty = tid >> 4;
    const int lk = tid & 15, lm = tid >> 4;
    const int m0 = blockIdx.y * 64, n0 = blockIdx.x * 64;
    float acc[4][4] = {};
    for (int k0 = 0; k0 < DD; k0 += 16) {
        #pragma unroll
        for (int r = 0; r < 4; ++r)
            As[lk][lm + 16*r] = Aq[(size_t)(m0 + lm + 16*r)*DD + k0 + lk];
        #pragma unroll
        for (int r = 0; r < 4; ++r)
            Bs[lk][lm + 16*r] = Bk[(size_t)(n0 + lm + 16*r)*DD + k0 + lk];
        __syncthreads();
        mm_tile(As, Bs, acc, tx, ty);
        __syncthreads();
    }
    #pragma unroll
    for (int i = 0; i < 4; ++i) {
        int gi = m0 + ty*4 + i;
        #pragma unroll
        for (int j = 0; j < 4; ++j) {
            int gj = n0 + tx*4 + j;
            C[(size_t)gi*CH + gj] = (gj <= gi) ? acc[i][j] : 0.f;
        }
    }
}

// batched: local = (A_chunk @ v_chunk + sq_chunk @ S_prefix) / den
__global__ void __launch_bounds__(256) attn_out_kernel()
{
    int bn = blockIdx.z; int b = bn >> 4, n = bn & 15;
    const float* Aq = d_sq   + (size_t)(b*SEQ + n*CH)*DD;
    const float* Sp = d_G    + (size_t)bn*DD*DD;
    const float* Am = d_Abuf + (size_t)bn*CH*CH;
    const float* Vc = d_v    + (size_t)(b*SEQ + n*CH)*DD;
    __shared__ float As[16][68], Bs[16][68];
    const int tid = threadIdx.x;
    const int tx = tid & 15, ty = tid >> 4;
    const int lk = tid & 15, lm = tid >> 4;
    const int ln = tid & 63, lk2 = tid >> 6;
    const int m0 = blockIdx.y * 64, n0 = blockIdx.x * 64;
    float acc[4][4] = {};
    // phase 1: sq @ S_prefix  (K = D)
    for (int k0 = 0; k0 < DD; k0 += 16) {
        #pragma unroll
        for (int r = 0; r < 4; ++r)
            As[lk][lm + 16*r] = Aq[(size_t)(m0 + lm + 16*r)*DD + k0 + lk];
        #pragma unroll
        for (int r = 0; r < 4; ++r)
            Bs[lk2 + 4*r][ln] = Sp[(size_t)(k0 + lk2 + 4*r)*DD + n0 + ln];
        __syncthreads();
        mm_tile(As, Bs, acc, tx, ty);
        __syncthreads();
    }
    // phase 2: A @ v  (K = CH)
    for (int k0 = 0; k0 < CH; k0 += 16) {
        #pragma unroll
        for (int r = 0; r < 4; ++r)
            As[lk][lm + 16*r] = Am[(size_t)(m0 + lm + 16*r)*CH + k0 + lk];
        #pragma unroll
        for (int r = 0; r < 4; ++r)
            Bs[lk2 + 4*r][ln] = Vc[(size_t)(k0 + lk2 + 4*r)*DD + n0 + ln];
        __syncthreads();
        mm_tile(As, Bs, acc, tx, ty);
        __syncthreads();
    }
    #pragma unroll
    for (int i = 0; i < 4; ++i) {
        int m = m0 + ty*4 + i;
        float inv = 1.f / d_den[bn*CH + m];
        #pragma unroll
        for (int j = 0; j < 4; ++j)
            d_local[(size_t)(b*SEQ + n*CH + m)*DD + n0 + tx*4 + j] = acc[i][j] * inv;
    }
}

// out = (g*memout + (1-g)*local) @ w_o^T
__global__ void __launch_bounds__(256) final_gemm(const float* __restrict__ Wo,
                                                  float* __restrict__ Out)
{
    __shared__ float As[16][68], Bs[16][68];
    const int tid = threadIdx.x;
    const int tx = tid & 15, ty = tid >> 4;
    const int lk = tid & 15, lm = tid >> 4;
    const int m0 = blockIdx.y * 64, n0 = blockIdx.x * 64;
    const float g = d_scal[0];
    const float og = 1.f - g;
    float acc[4][4] = {};
    for (int k0 = 0; k0 < DD; k0 += 16) {
        #pragma unroll
        for (int r = 0; r < 4; ++r) {
            size_t idx = (size_t)(m0 + lm + 16*r)*DD + k0 + lk;
            As[lk][lm + 16*r] = g * d_memout[idx] + og * d_local[idx];
        }
        #pragma unroll
        for (int r = 0; r < 4; ++r)
            Bs[lk][lm + 16*r] = Wo[(size_t)(n0 + lm + 16*r)*DD + k0 + lk];
        __syncthreads();
        mm_tile(As, Bs, acc, tx, ty);
        __syncthreads();
    }
    #pragma unroll
    for (int i = 0; i < 4; ++i) {
        int m = m0 + ty*4 + i;
        #pragma unroll
        for (int j = 0; j < 4; ++j)
            Out[(size_t)m*DD + n0 + tx*4 + j] = acc[i][j];
    }
}

// ---------------- launcher ----------------
extern "C" void kernel_launch(void* const* d_in, const int* in_sizes, int n_in,
                              void* d_out, int out_size) {
    const float* hs    = (const float*)d_in[0];
    const float* wq    = (const float*)d_in[1];
    const float* wk    = (const float*)d_in[2];
    const float* wv    = (const float*)d_in[3];
    const float* wo    = (const float*)d_in[4];
    const float* gate  = (const float*)d_in[5];
    const float* mem   = (const float*)d_in[6];
    const float* mnorm = (const float*)d_in[7];
    float* out = (float*)d_out;

    scalars_kernel<<<1, 1024>>>(gate, mnorm);

    dim3 gP(DD/64, MTOT/64);            // (16, 64)
    gemm_proj<0><<<gP, 256>>>(hs, wq, MTOT, DD, DD);   // sq = elu1(hs @ wq^T)
    gemm_proj<1><<<gP, 256>>>(hs, wk, MTOT, DD, DD);   // sk = elu1(hs @ wk^T)
    gemm_proj<2><<<gP, 256>>>(hs, wv, MTOT, DD, DD);   // v  = hs @ wv^T

    normq_kernel<<<(MTOT*32 + 255)/256, 256>>>(mnorm);
    gemm_memout<<<gP, 256>>>(mem);

    zc_kernel<<<(BSZ*NCH*DD + 255)/256, 256>>>();
    zprefix_kernel<<<(BSZ*DD + 255)/256, 256>>>();

    dim3 gKV(DD/64, DD/64, BSZ*NCH);    // (16,16,32)
    gemm_kv<<<gKV, 256>>>();
    gprefix_kernel<<<(BSZ*DD*DD + 255)/256, 256>>>();

    dim3 gSc(CH/64, CH/64, BSZ*NCH);    // (2,2,32)
    gemm_scores<<<gSc, 256>>>();
    den_kernel<<<(BSZ*NCH*CH*32 + 255)/256, 256>>>();

    dim3 gOut(DD/64, CH/64, BSZ*NCH);   // (16,2,32)
    attn_out_kernel<<<gOut, 256>>>();

    final_gemm<<<gP, 256>>>(wo, out);
}

// round 3
// speedup vs baseline: 2.4325x; 2.4325x over previous
#include <cuda_runtime.h>
#include <cuda_bf16.h>
#include <math.h>
#include <stdint.h>

#define BSZ 2
#define SEQ 2048
#define DD 1024
#define CH 128
#define NCH 16
#define MTOT (BSZ*SEQ)        // 4096
#define EPSV 1e-6f
#define PAD 40                // smem row stride in bf16 (80B, 16B-aligned, conflict-free ldmatrix)

// ---------------- scratch (device globals; no allocation allowed) ----------------
__device__ float d_sq[MTOT*DD];
__device__ float d_sk[MTOT*DD];
__device__ float d_v [MTOT*DD];
__device__ float d_memout[MTOT*DD];
__device__ float d_local[MTOT*DD];
__device__ float d_G[(size_t)BSZ*NCH*DD*DD];
__device__ float d_zz[BSZ*NCH*DD];
__device__ float d_Abuf[BSZ*NCH*CH*CH];
__device__ float d_den[BSZ*NCH*CH];
__device__ float d_normq[MTOT];
__device__ float d_scal[2];

// ---------------- small kernels (unchanged from R1) ----------------
__global__ void scalars_kernel(const float* __restrict__ gate,
                               const float* __restrict__ mnorm) {
    __shared__ float sh[1024];
    int t = threadIdx.x;
    sh[t] = mnorm[t];
    __syncthreads();
    for (int s = 512; s > 0; s >>= 1) { if (t < s) sh[t] += sh[t+s]; __syncthreads(); }
    if (t == 0) {
        d_scal[0] = 1.f / (1.f + expf(-gate[0]));
        d_scal[1] = (sh[0] >= EPSV) ? 1.f : 0.f;
    }
}

__global__ void normq_kernel(const float* __restrict__ mnorm) {
    int warp = (blockIdx.x * blockDim.x + threadIdx.x) >> 5;
    int lane = threadIdx.x & 31;
    if (warp >= MTOT) return;
    const float* row = d_sq + (size_t)warp * DD;
    float s = 0.f;
    for (int k = lane; k < DD; k += 32) s += row[k] * mnorm[k];
    #pragma unroll
    for (int o = 16; o > 0; o >>= 1) s += __shfl_xor_sync(0xffffffffu, s, o);
    if (lane == 0) d_normq[warp] = fmaxf(s, EPSV);
}

__global__ void zc_kernel() {
    int idx = blockIdx.x * blockDim.x + threadIdx.x;
    if (idx >= BSZ*NCH*DD) return;
    int d = idx % DD; int bn = idx / DD;
    int b = bn >> 4, n = bn & 15;
    const float* base = d_sk + (size_t)(b*SEQ + n*CH)*DD + d;
    float s = 0.f;
    #pragma unroll 4
    for (int i = 0; i < CH; ++i) s += base[(size_t)i*DD];
    d_zz[idx] = s;
}

__global__ void zprefix_kernel() {
    int idx = blockIdx.x * blockDim.x + threadIdx.x;
    if (idx >= BSZ*DD) return;
    int b = idx / DD, d = idx % DD;
    float run = 0.f;
    for (int n = 0; n < NCH; ++n) {
        float* p = d_zz + (size_t)(b*NCH + n)*DD + d;
        float t = *p; *p = run; run += t;
    }
}

__global__ void gprefix_kernel() {
    size_t idx = (size_t)blockIdx.x * blockDim.x + threadIdx.x;
    if (idx >= (size_t)BSZ*DD*DD) return;
    int b = (int)(idx / ((size_t)DD*DD));
    size_t rem = idx % ((size_t)DD*DD);
    float run = 0.f;
    for (int n = 0; n < NCH; ++n) {
        float* p = d_G + ((size_t)(b*NCH + n)*DD*DD) + rem;
        float t = *p; *p = run; run += t;
    }
}

__global__ void den_kernel() {
    int warp = (blockIdx.x * blockDim.x + threadIdx.x) >> 5;
    int lane = threadIdx.x & 31;
    if (warp >= BSZ*NCH*CH) return;
    int bn = warp / CH, i = warp % CH;
    int b = bn >> 4, n = bn & 15;
    const float* qr = d_sq + (size_t)(b*SEQ + n*CH + i)*DD;
    const float* zr = d_zz + (size_t)bn*DD;
    float s = 0.f;
    for (int k = lane; k < DD; k += 32) s += qr[k] * zr[k];
    const float* ar = d_Abuf + (size_t)bn*CH*CH + (size_t)i*CH;
    for (int j = lane; j < CH; j += 32) s += ar[j];
    #pragma unroll
    for (int o = 16; o > 0; o >>= 1) s += __shfl_xor_sync(0xffffffffu, s, o);
    if (lane == 0) d_den[warp] = fmaxf(s, EPSV);
}

__global__ void combine_kernel() {
    size_t i = ((size_t)blockIdx.x * blockDim.x + threadIdx.x) * 4;
    if (i >= (size_t)MTOT*DD) return;
    float g = d_scal[0], og = 1.f - g;
    float4 a = *(float4*)&d_memout[i];
    float4 b = *(float4*)&d_local[i];
    a.x = g*a.x + og*b.x;  a.y = g*a.y + og*b.y;
    a.z = g*a.z + og*b.z;  a.w = g*a.w + og*b.w;
    *(float4*)&d_memout[i] = a;
}

// ---------------- tensor-core GEMM core (bf16x3 split precision) ----------------
// Block tile 128(M) x 64(N), K-step 32, 256 threads = 8 warps (4 along M x 2 along N).
// Warp tile 32x32: 2 m16 tiles x 4 n8 tiles, mma.sync.m16n8k16.bf16.

__device__ __forceinline__ void ldsm4(uint32_t* r, const __nv_bfloat16* p) {
    uint32_t a = (uint32_t)__cvta_generic_to_shared(p);
    asm volatile("ldmatrix.sync.aligned.m8n8.x4.shared.b16 {%0,%1,%2,%3}, [%4];"
        : "=r"(r[0]), "=r"(r[1]), "=r"(r[2]), "=r"(r[3]) : "r"(a));
}
__device__ __forceinline__ void ldsm2(uint32_t* r, const __nv_bfloat16* p) {
    uint32_t a = (uint32_t)__cvta_generic_to_shared(p);
    asm volatile("ldmatrix.sync.aligned.m8n8.x2.shared.b16 {%0,%1}, [%2];"
        : "=r"(r[0]), "=r"(r[1]) : "r"(a));
}
__device__ __forceinline__ void mma_bf16(float* c, const uint32_t* a, const uint32_t* b) {
    asm volatile("mma.sync.aligned.m16n8k16.row.col.f32.bf16.bf16.f32 "
        "{%0,%1,%2,%3}, {%4,%5,%6,%7}, {%8,%9}, {%0,%1,%2,%3};"
        : "+f"(c[0]), "+f"(c[1]), "+f"(c[2]), "+f"(c[3])
        : "r"(a[0]), "r"(a[1]), "r"(a[2]), "r"(a[3]), "r"(b[0]), "r"(b[1]));
}

__device__ __forceinline__ void cvt1(float x, __nv_bfloat16* h, __nv_bfloat16* l) {
    __nv_bfloat16 hi = __float2bfloat16(x);
    *h = hi;
    *l = __float2bfloat16(x - __bfloat162float(hi));
}
__device__ __forceinline__ void cvt4(float4 x, __nv_bfloat16* hp, __nv_bfloat16* lp) {
    __nv_bfloat16 h0, h1, h2, h3, l0, l1, l2, l3;
    cvt1(x.x, &h0, &l0); cvt1(x.y, &h1, &l1);
    cvt1(x.z, &h2, &l2); cvt1(x.w, &h3, &l3);
    union { __nv_bfloat162 b[2]; uint2 u; } uh, ul;
    uh.b[0] = __halves2bfloat162(h0, h1); uh.b[1] = __halves2bfloat162(h2, h3);
    ul.b[0] = __halves2bfloat162(l0, l1); ul.b[1] = __halves2bfloat162(l2, l3);
    *(uint2*)hp = uh.u;
    *(uint2*)lp = ul.u;
}

struct Op { const float* p; int ld; int trans; };  // trans=0: gmem[row][K]; trans=1: gmem[K][row]

__device__ __forceinline__ void stage_A(Op A, int k0, __nv_bfloat16* Ah, __nv_bfloat16* Al, int tid) {
    if (!A.trans) {
        #pragma unroll
        for (int i = 0; i < 4; ++i) {
            int r = (tid >> 3) + 32*i, kq = (tid & 7);
            float4 x = *(const float4*)(A.p + (size_t)r*A.ld + k0 + kq*4);
            cvt4(x, Ah + r*PAD + kq*4, Al + r*PAD + kq*4);
        }
    } else {
        #pragma unroll
        for (int i = 0; i < 16; ++i) {
            int idx = tid + 256*i;
            int k = idx >> 7, m = idx & 127;
            float x = A.p[(size_t)(k0 + k)*A.ld + m];
            cvt1(x, Ah + m*PAD + k, Al + m*PAD + k);
        }
    }
}
__device__ __forceinline__ void stage_B(Op B, int k0, __nv_bfloat16* Bh, __nv_bfloat16* Bl, int tid) {
    if (!B.trans) {
        #pragma unroll
        for (int i = 0; i < 2; ++i) {
            int r = (tid >> 3) + 32*i, kq = (tid & 7);
            float4 x = *(const float4*)(B.p + (size_t)r*B.ld + k0 + kq*4);
            cvt4(x, Bh + r*PAD + kq*4, Bl + r*PAD + kq*4);
        }
    } else {
        #pragma unroll
        for (int i = 0; i < 8; ++i) {
            int idx = tid + 256*i;
            int k = idx >> 6, n = idx & 63;
            float x = B.p[(size_t)(k0 + k)*B.ld + n];
            cvt1(x, Bh + n*PAD + k, Bl + n*PAD + k);
        }
    }
}

// Accumulates into acc (call twice for two-phase GEMMs).
__device__ __forceinline__ void gemm_core(Op A, Op B, int K, float acc[2][4][4],
                                          __nv_bfloat16* Ah, __nv_bfloat16* Al,
                                          __nv_bfloat16* Bh, __nv_bfloat16* Bl, int tid) {
    const int lane = tid & 31, wid = tid >> 5;
    const int wm = (wid & 3) * 32, wn = (wid >> 2) * 32;
    for (int k0 = 0; k0 < K; k0 += 32) {
        stage_A(A, k0, Ah, Al, tid);
        stage_B(B, k0, Bh, Bl, tid);
        __syncthreads();
        #pragma unroll
        for (int ks = 0; ks < 32; ks += 16) {
            uint32_t ah[2][4], al[2][4], bh[4][2], bl[4][2];
            #pragma unroll
            for (int mt = 0; mt < 2; ++mt) {
                int row = wm + mt*16 + (lane & 15);
                int ko  = ks + ((lane >> 4) << 3);
                ldsm4(ah[mt], Ah + row*PAD + ko);
                ldsm4(al[mt], Al + row*PAD + ko);
            }
            #pragma unroll
            for (int nt = 0; nt < 4; ++nt) {
                int row = wn + nt*8 + (lane & 7);
                int ko  = ks + (((lane >> 3) & 1) << 3);
                ldsm2(bh[nt], Bh + row*PAD + ko);
                ldsm2(bl[nt], Bl + row*PAD + ko);
            }
            #pragma unroll
            for (int mt = 0; mt < 2; ++mt)
                #pragma unroll
                for (int nt = 0; nt < 4; ++nt) {
                    mma_bf16(acc[mt][nt], ah[mt], bh[nt]);
                    mma_bf16(acc[mt][nt], ah[mt], bl[nt]);
                    mma_bf16(acc[mt][nt], al[mt], bh[nt]);
                }
        }
        __syncthreads();
    }
}

#define GEMM_SMEM \
    __shared__ __align__(16) __nv_bfloat16 sm_[(128+128+64+64)*PAD]; \
    __nv_bfloat16* Ah = sm_; \
    __nv_bfloat16* Al = sm_ + 128*PAD; \
    __nv_bfloat16* Bh = sm_ + 256*PAD; \
    __nv_bfloat16* Bl = sm_ + 320*PAD;

// Per-thread output coordinates for acc[mt][nt][ci]
#define EPI_COORDS \
    const int lane = tid & 31, wid = tid >> 5; \
    const int gid = lane >> 2, tig = lane & 3; \
    const int wm = (wid & 3) * 32, wn = (wid >> 2) * 32;

// ---------------- GEMM kernels ----------------
// q/k/v projections: C = hs @ W^T, epilogue elu+1 for q,k
template<int WHICH>
__global__ void __launch_bounds__(256) tc_proj(const float* __restrict__ hs,
                                               const float* __restrict__ W) {
    GEMM_SMEM;
    int tid = threadIdx.x;
    int m0 = blockIdx.y * 128, n0 = blockIdx.x * 64;
    float acc[2][4][4] = {};
    Op A{hs + (size_t)m0*DD, DD, 0};
    Op B{W  + (size_t)n0*DD, DD, 0};
    gemm_core(A, B, DD, acc, Ah, Al, Bh, Bl, tid);
    float* C = (WHICH == 0) ? d_sq : (WHICH == 1) ? d_sk : d_v;
    EPI_COORDS;
    #pragma unroll
    for (int mt = 0; mt < 2; ++mt)
        #pragma unroll
        for (int nt = 0; nt < 4; ++nt)
            #pragma unroll
            for (int ci = 0; ci < 4; ++ci) {
                int m = m0 + wm + mt*16 + gid + ((ci >> 1) ? 8 : 0);
                int n = n0 + wn + nt*8 + tig*2 + (ci & 1);
                float v = acc[mt][nt][ci];
                if (WHICH < 2) v = (v > 0.f) ? v + 1.f : expf(v);
                C[(size_t)m*DD + n] = v;
            }
}

// memout = active * (sq @ memory) / normq
__global__ void __launch_bounds__(256) tc_memout(const float* __restrict__ mem) {
    GEMM_SMEM;
    int tid = threadIdx.x;
    int m0 = blockIdx.y * 128, n0 = blockIdx.x * 64;
    float acc[2][4][4] = {};
    Op A{d_sq + (size_t)m0*DD, DD, 0};
    Op B{mem + n0, DD, 1};
    gemm_core(A, B, DD, acc, Ah, Al, Bh, Bl, tid);
    float act = d_scal[1];
    EPI_COORDS;
    #pragma unroll
    for (int mt = 0; mt < 2; ++mt)
        #pragma unroll
        for (int nt = 0; nt < 4; ++nt)
            #pragma unroll
            for (int ci = 0; ci < 4; ++ci) {
                int m = m0 + wm + mt*16 + gid + ((ci >> 1) ? 8 : 0);
                int n = n0 + wn + nt*8 + tig*2 + (ci & 1);
                d_memout[(size_t)m*DD + n] = acc[mt][nt][ci] * act / d_normq[m];
            }
}

// per-chunk G = sk^T @ v
__global__ void __launch_bounds__(256) tc_kv() {
    GEMM_SMEM;
    int tid = threadIdx.x;
    int bn = blockIdx.z; int b = bn >> 4, n = bn & 15;
    size_t cb = (size_t)(b*SEQ + n*CH)*DD;
    int m0 = blockIdx.y * 128, n0 = blockIdx.x * 64;
    float acc[2][4][4] = {};
    Op A{d_sk + cb + m0, DD, 1};
    Op B{d_v  + cb + n0, DD, 1};
    gemm_core(A, B, CH, acc, Ah, Al, Bh, Bl, tid);
    float* C = d_G + (size_t)bn*DD*DD;
    EPI_COORDS;
    #pragma unroll
    for (int mt = 0; mt < 2; ++mt)
        #pragma unroll
        for (int nt = 0; nt < 4; ++nt)
            #pragma unroll
            for (int ci = 0; ci < 4; ++ci) {
                int m = m0 + wm + mt*16 + gid + ((ci >> 1) ? 8 : 0);
                int nn = n0 + wn + nt*8 + tig*2 + (ci & 1);
                C[(size_t)m*DD + nn] = acc[mt][nt][ci];
            }
}

// per-chunk masked scores A = tril(sq @ sk^T)
__global__ void __launch_bounds__(256) tc_scores() {
    GEMM_SMEM;
    int tid = threadIdx.x;
    int bn = blockIdx.z; int b = bn >> 4, n = bn & 15;
    size_t cb = (size_t)(b*SEQ + n*CH)*DD;
    int n0 = blockIdx.x * 64;
    float acc[2][4][4] = {};
    Op A{d_sq + cb, DD, 0};
    Op B{d_sk + cb + (size_t)n0*DD, DD, 0};
    gemm_core(A, B, DD, acc, Ah, Al, Bh, Bl, tid);
    float* C = d_Abuf + (size_t)bn*CH*CH;
    EPI_COORDS;
    #pragma unroll
    for (int mt = 0; mt < 2; ++mt)
        #pragma unroll
        for (int nt = 0; nt < 4; ++nt)
            #pragma unroll
            for (int ci = 0; ci < 4; ++ci) {
                int gi = wm + mt*16 + gid + ((ci >> 1) ? 8 : 0);
                int gj = n0 + wn + nt*8 + tig*2 + (ci & 1);
                C[(size_t)gi*CH + gj] = (gj <= gi) ? acc[mt][nt][ci] : 0.f;
            }
}

// per-chunk local = (Abuf @ v + sq @ Sp) / den
__global__ void __launch_bounds__(256) tc_attn() {
    GEMM_SMEM;
    int tid = threadIdx.x;
    int bn = blockIdx.z; int b = bn >> 4, n = bn & 15;
    size_t cb = (size_t)(b*SEQ + n*CH)*DD;
    int n0 = blockIdx.x * 64;
    float acc[2][4][4] = {};
    Op A1{d_sq + cb, DD, 0};
    Op B1{d_G + (size_t)bn*DD*DD + n0, DD, 1};
    gemm_core(A1, B1, DD, acc, Ah, Al, Bh, Bl, tid);
    Op A2{d_Abuf + (size_t)bn*CH*CH, CH, 0};
    Op B2{d_v + cb + n0, DD, 1};
    gemm_core(A2, B2, CH, acc, Ah, Al, Bh, Bl, tid);
    EPI_COORDS;
    #pragma unroll
    for (int mt = 0; mt < 2; ++mt)
        #pragma unroll
        for (int nt = 0; nt < 4; ++nt)
            #pragma unroll
            for (int ci = 0; ci < 4; ++ci) {
                int m = wm + mt*16 + gid + ((ci >> 1) ? 8 : 0);
                int nn = n0 + wn + nt*8 + tig*2 + (ci & 1);
                d_local[cb + (size_t)m*DD + nn] = acc[mt][nt][ci] / d_den[bn*CH + m];
            }
}

// out = comb @ wo^T  (comb precomputed into d_memout)
__global__ void __launch_bounds__(256) tc_final(const float* __restrict__ Wo,
                                                float* __restrict__ Out) {
    GEMM_SMEM;
    int tid = threadIdx.x;
    int m0 = blockIdx.y * 128, n0 = blockIdx.x * 64;
    float acc[2][4][4] = {};
    Op A{d_memout + (size_t)m0*DD, DD, 0};
    Op B{Wo + (size_t)n0*DD, DD, 0};
    gemm_core(A, B, DD, acc, Ah, Al, Bh, Bl, tid);
    EPI_COORDS;
    #pragma unroll
    for (int mt = 0; mt < 2; ++mt)
        #pragma unroll
        for (int nt = 0; nt < 4; ++nt)
            #pragma unroll
            for (int ci = 0; ci < 4; ++ci) {
                int m = m0 + wm + mt*16 + gid + ((ci >> 1) ? 8 : 0);
                int n = n0 + wn + nt*8 + tig*2 + (ci & 1);
                Out[(size_t)m*DD + n] = acc[mt][nt][ci];
            }
}

// ---------------- launcher ----------------
extern "C" void kernel_launch(void* const* d_in, const int* in_sizes, int n_in,
                              void* d_out, int out_size) {
    const float* hs    = (const float*)d_in[0];
    const float* wq    = (const float*)d_in[1];
    const float* wk    = (const float*)d_in[2];
    const float* wv    = (const float*)d_in[3];
    const float* wo    = (const float*)d_in[4];
    const float* gate  = (const float*)d_in[5];
    const float* mem   = (const float*)d_in[6];
    const float* mnorm = (const float*)d_in[7];
    float* out = (float*)d_out;

    scalars_kernel<<<1, 1024>>>(gate, mnorm);

    dim3 gP(DD/64, MTOT/128);           // (16, 32)
    tc_proj<0><<<gP, 256>>>(hs, wq);
    tc_proj<1><<<gP, 256>>>(hs, wk);
    tc_proj<2><<<gP, 256>>>(hs, wv);

    normq_kernel<<<(MTOT*32 + 255)/256, 256>>>(mnorm);
    tc_memout<<<gP, 256>>>(mem);

    zc_kernel<<<(BSZ*NCH*DD + 255)/256, 256>>>();
    zprefix_kernel<<<(BSZ*DD + 255)/256, 256>>>();

    dim3 gKV(DD/64, DD/128, BSZ*NCH);   // (16, 8, 32)
    tc_kv<<<gKV, 256>>>();
    gprefix_kernel<<<((size_t)BSZ*DD*DD + 255)/256, 256>>>();

    dim3 gSc(CH/64, 1, BSZ*NCH);        // (2, 1, 32)
    tc_scores<<<gSc, 256>>>();
    den_kernel<<<(BSZ*NCH*CH*32 + 255)/256, 256>>>();

    dim3 gAt(DD/64, 1, BSZ*NCH);        // (16, 1, 32)
    tc_attn<<<gAt, 256>>>();

    combine_kernel<<<(MTOT*DD/4 + 255)/256, 256>>>();
    tc_final<<<gP, 256>>>(wo, out);
}

// round 4
// speedup vs baseline: 3.1324x; 1.2877x over previous
#include <cuda_runtime.h>
#include <cuda_bf16.h>
#include <math.h>
#include <stdint.h>

#define BSZ 2
#define SEQ 2048
#define DD 1024
#define CH 128
#define NCH 16
#define MTOT (BSZ*SEQ)        // 4096
#define EPSV 1e-6f

typedef __nv_bfloat16 bf16;

// ---------------- scratch (device globals; no allocation allowed) ----------------
__device__ float d_sq[MTOT*DD];                  // fp32 (normq/den)
__device__ float d_sk[MTOT*DD];                  // fp32 (zc)
__device__ float d_memout[MTOT*DD];
__device__ float d_local[MTOT*DD];
__device__ float d_G[(size_t)BSZ*NCH*DD*DD];     // fp32 per-chunk KV, prefixed by gprefix
__device__ float d_zz[BSZ*NCH*DD];
__device__ float d_Abuf[BSZ*NCH*CH*CH];          // fp32 (den)
__device__ float d_den[BSZ*NCH*CH];
__device__ float d_normq[MTOT];
__device__ float d_scal[2];

// bf16 hi/lo operand buffers
__device__ bf16 d_hsh[MTOT*DD],  d_hsl[MTOT*DD];
__device__ bf16 d_wqh[DD*DD],    d_wql[DD*DD];
__device__ bf16 d_wkh[DD*DD],    d_wkl[DD*DD];
__device__ bf16 d_wvh[DD*DD],    d_wvl[DD*DD];
__device__ bf16 d_woh[DD*DD],    d_wol[DD*DD];
__device__ bf16 d_memTh[DD*DD],  d_memTl[DD*DD];   // memory transposed [N][K]
__device__ bf16 d_sqh[MTOT*DD],  d_sql[MTOT*DD];
__device__ bf16 d_skh[MTOT*DD],  d_skl[MTOT*DD];
__device__ bf16 d_vh [MTOT*DD],  d_vl [MTOT*DD];
__device__ bf16 d_Sph[(size_t)BSZ*NCH*DD*DD], d_Spl[(size_t)BSZ*NCH*DD*DD]; // exclusive prefix of G
__device__ bf16 d_Abh[BSZ*NCH*CH*CH], d_Abl[BSZ*NCH*CH*CH];
__device__ bf16 d_cmh[MTOT*DD],  d_cml[MTOT*DD];

// ---------------- helpers ----------------
__device__ __forceinline__ void split1(float x, bf16& h, bf16& l) {
    h = __float2bfloat16(x);
    l = __float2bfloat16(x - __bfloat162float(h));
}
__device__ __forceinline__ void wsplit(bf16* H, bf16* L, size_t i, float v) {
    bf16 h, l; split1(v, h, l); H[i] = h; L[i] = l;
}

// ---------------- small kernels ----------------
__global__ void scalars_kernel(const float* __restrict__ gate,
                               const float* __restrict__ mnorm) {
    __shared__ float sh[1024];
    int t = threadIdx.x;
    sh[t] = mnorm[t];
    __syncthreads();
    for (int s = 512; s > 0; s >>= 1) { if (t < s) sh[t] += sh[t+s]; __syncthreads(); }
    if (t == 0) {
        d_scal[0] = 1.f / (1.f + expf(-gate[0]));
        d_scal[1] = (sh[0] >= EPSV) ? 1.f : 0.f;
    }
}

__global__ void cvt_split_k(const float4* __restrict__ src, uint2* __restrict__ hi,
                            uint2* __restrict__ lo, int n4) {
    int i = blockIdx.x * blockDim.x + threadIdx.x;
    if (i >= n4) return;
    float4 x = src[i];
    bf16 h0,h1,h2,h3,l0,l1,l2,l3;
    split1(x.x,h0,l0); split1(x.y,h1,l1); split1(x.z,h2,l2); split1(x.w,h3,l3);
    union { __nv_bfloat162 b[2]; uint2 u; } uh, ul;
    uh.b[0] = __halves2bfloat162(h0,h1); uh.b[1] = __halves2bfloat162(h2,h3);
    ul.b[0] = __halves2bfloat162(l0,l1); ul.b[1] = __halves2bfloat162(l2,l3);
    hi[i] = uh.u; lo[i] = ul.u;
}

// memT[n][k] = mem[k][n]
__global__ void cvt_T_k(const float* __restrict__ src) {
    int idx = blockIdx.x * blockDim.x + threadIdx.x;
    if (idx >= DD*DD) return;
    int k = idx & (DD-1), n = idx >> 10;
    wsplit(d_memTh, d_memTl, (size_t)n*DD + k, src[(size_t)k*DD + n]);
}

__global__ void normq_kernel(const float* __restrict__ mnorm) {
    int warp = (blockIdx.x * blockDim.x + threadIdx.x) >> 5;
    int lane = threadIdx.x & 31;
    if (warp >= MTOT) return;
    const float* row = d_sq + (size_t)warp * DD;
    float s = 0.f;
    for (int k = lane; k < DD; k += 32) s += row[k] * mnorm[k];
    #pragma unroll
    for (int o = 16; o > 0; o >>= 1) s += __shfl_xor_sync(0xffffffffu, s, o);
    if (lane == 0) d_normq[warp] = fmaxf(s, EPSV);
}

__global__ void zc_kernel() {
    int idx = blockIdx.x * blockDim.x + threadIdx.x;
    if (idx >= BSZ*NCH*DD) return;
    int d = idx % DD; int bn = idx / DD;
    int b = bn >> 4, n = bn & 15;
    const float* base = d_sk + (size_t)(b*SEQ + n*CH)*DD + d;
    float s = 0.f;
    #pragma unroll 4
    for (int i = 0; i < CH; ++i) s += base[(size_t)i*DD];
    d_zz[idx] = s;
}

__global__ void zprefix_kernel() {
    int idx = blockIdx.x * blockDim.x + threadIdx.x;
    if (idx >= BSZ*DD) return;
    int b = idx / DD, d = idx % DD;
    float run = 0.f;
    for (int n = 0; n < NCH; ++n) {
        float* p = d_zz + (size_t)(b*NCH + n)*DD + d;
        float t = *p; *p = run; run += t;
    }
}

// exclusive prefix of G over chunks -> Sp hi/lo bf16
__global__ void gprefix_kernel() {
    size_t idx = (size_t)blockIdx.x * blockDim.x + threadIdx.x;
    if (idx >= (size_t)BSZ*DD*DD) return;
    int b = (int)(idx / ((size_t)DD*DD));
    size_t rem = idx % ((size_t)DD*DD);
    float run = 0.f;
    for (int n = 0; n < NCH; ++n) {
        size_t off = ((size_t)(b*NCH + n)*DD*DD) + rem;
        float t = d_G[off];
        wsplit(d_Sph, d_Spl, off, run);
        run += t;
    }
}

__global__ void den_kernel() {
    int warp = (blockIdx.x * blockDim.x + threadIdx.x) >> 5;
    int lane = threadIdx.x & 31;
    if (warp >= BSZ*NCH*CH) return;
    int bn = warp / CH, i = warp % CH;
    int b = bn >> 4, n = bn & 15;
    const float* qr = d_sq + (size_t)(b*SEQ + n*CH + i)*DD;
    const float* zr = d_zz + (size_t)bn*DD;
    float s = 0.f;
    for (int k = lane; k < DD; k += 32) s += qr[k] * zr[k];
    const float* ar = d_Abuf + (size_t)bn*CH*CH + (size_t)i*CH;
    for (int j = lane; j < CH; j += 32) s += ar[j];
    #pragma unroll
    for (int o = 16; o > 0; o >>= 1) s += __shfl_xor_sync(0xffffffffu, s, o);
    if (lane == 0) d_den[warp] = fmaxf(s, EPSV);
}

__global__ void combine_kernel() {
    size_t i = ((size_t)blockIdx.x * blockDim.x + threadIdx.x);
    if (i >= (size_t)MTOT*DD) return;
    float g = d_scal[0], og = 1.f - g;
    wsplit(d_cmh, d_cml, i, g * d_memout[i] + og * d_local[i]);
}

// ---------------- tensor-core GEMM core ----------------
// Block tile 128(M) x 64(N), K-step 16, 256 thr = 8 warps (4M x 2N), warp tile 32x32.
// bf16x3: C += Ah*Bh + Ah*Bl + Al*Bh. cp.async double-buffered staging.

#define NT_STRIDE 24     // [rows][16 k + 8 pad] bf16
#define TA_STRIDE 136    // trans A: [16 k][128 m + 8 pad]
#define TB_STRIDE 72     // trans B: [16 k][64 n + 8 pad]
#define A_HALF_B 6144    // bytes: max(128*24, 16*136)*2
#define B_HALF_B 3072    // bytes: max(64*24, 16*72)*2
#define STAGE_B (2*A_HALF_B + 2*B_HALF_B)   // 18432

__device__ __forceinline__ void cpa16(void* dst, const void* src) {
    uint32_t d = (uint32_t)__cvta_generic_to_shared(dst);
    asm volatile("cp.async.cg.shared.global [%0], [%1], 16;" :: "r"(d), "l"(src));
}
__device__ __forceinline__ void cp_commit() { asm volatile("cp.async.commit_group;"); }
__device__ __forceinline__ void cp_wait1()  { asm volatile("cp.async.wait_group 1;"); }

__device__ __forceinline__ void ldsm4(uint32_t* r, const bf16* p) {
    uint32_t a = (uint32_t)__cvta_generic_to_shared(p);
    asm volatile("ldmatrix.sync.aligned.m8n8.x4.shared.b16 {%0,%1,%2,%3}, [%4];"
        : "=r"(r[0]), "=r"(r[1]), "=r"(r[2]), "=r"(r[3]) : "r"(a));
}
__device__ __forceinline__ void ldsm4t(uint32_t* r, const bf16* p) {
    uint32_t a = (uint32_t)__cvta_generic_to_shared(p);
    asm volatile("ldmatrix.sync.aligned.m8n8.x4.trans.shared.b16 {%0,%1,%2,%3}, [%4];"
        : "=r"(r[0]), "=r"(r[1]), "=r"(r[2]), "=r"(r[3]) : "r"(a));
}
__device__ __forceinline__ void ldsm2(uint32_t* r, const bf16* p) {
    uint32_t a = (uint32_t)__cvta_generic_to_shared(p);
    asm volatile("ldmatrix.sync.aligned.m8n8.x2.shared.b16 {%0,%1}, [%2];"
        : "=r"(r[0]), "=r"(r[1]) : "r"(a));
}
__device__ __forceinline__ void ldsm2t(uint32_t* r, const bf16* p) {
    uint32_t a = (uint32_t)__cvta_generic_to_shared(p);
    asm volatile("ldmatrix.sync.aligned.m8n8.x2.trans.shared.b16 {%0,%1}, [%2];"
        : "=r"(r[0]), "=r"(r[1]) : "r"(a));
}
__device__ __forceinline__ void mma_bf16(float* c, const uint32_t* a, const uint32_t* b) {
    asm volatile("mma.sync.aligned.m16n8k16.row.col.f32.bf16.bf16.f32 "
        "{%0,%1,%2,%3}, {%4,%5,%6,%7}, {%8,%9}, {%0,%1,%2,%3};"
        : "+f"(c[0]), "+f"(c[1]), "+f"(c[2]), "+f"(c[3])
        : "r"(a[0]), "r"(a[1]), "r"(a[2]), "r"(a[3]), "r"(b[0]), "r"(b[1]));
}

struct Op { const bf16 *h, *l; int ld; };  // pointers pre-offset to tile origin

// stage one K-step-16 tile (A: 128 rows or 16x128; B: 64 rows or 16x64)
template<int TA, int TB>
__device__ __forceinline__ void stage(Op A, Op B, int k0, char* sm, int tid) {
    bf16* Ah = (bf16*)sm;
    bf16* Al = (bf16*)(sm + A_HALF_B);
    bf16* Bh = (bf16*)(sm + 2*A_HALF_B);
    bf16* Bl = (bf16*)(sm + 2*A_HALF_B + B_HALF_B);
    if (!TA) {
        int row = tid >> 1, ch = tid & 1;            // 128 rows x 2 chunks
        size_t so = (size_t)row * A.ld + k0 + ch*8;
        cpa16(Ah + row*NT_STRIDE + ch*8, A.h + so);
        cpa16(Al + row*NT_STRIDE + ch*8, A.l + so);
    } else {
        int row = tid >> 4, ch = tid & 15;           // 16 k-rows x 16 chunks (128 m)
        size_t so = (size_t)(k0 + row) * A.ld + ch*8;
        cpa16(Ah + row*TA_STRIDE + ch*8, A.h + so);
        cpa16(Al + row*TA_STRIDE + ch*8, A.l + so);
    }
    if (tid < 128) {
        if (!TB) {
            int row = tid >> 1, ch = tid & 1;        // 64 rows x 2 chunks
            size_t so = (size_t)row * B.ld + k0 + ch*8;
            cpa16(Bh + row*NT_STRIDE + ch*8, B.h + so);
            cpa16(Bl + row*NT_STRIDE + ch*8, B.l + so);
        } else {
            int row = tid >> 3, ch = tid & 7;        // 16 k-rows x 8 chunks (64 n)
            size_t so = (size_t)(k0 + row) * B.ld + ch*8;
            cpa16(Bh + row*TB_STRIDE + ch*8, B.h + so);
            cpa16(Bl + row*TB_STRIDE + ch*8, B.l + so);
        }
    }
}

template<int TA, int TB>
__device__ __forceinline__ void compute16(char* sm, float acc[2][4][4], int lane, int wm, int wn) {
    bf16* Ah = (bf16*)sm;
    bf16* Al = (bf16*)(sm + A_HALF_B);
    bf16* Bh = (bf16*)(sm + 2*A_HALF_B);
    bf16* Bl = (bf16*)(sm + 2*A_HALF_B + B_HALF_B);
    uint32_t ah[2][4], al[2][4], bh[4][2], bl[4][2];
    #pragma unroll
    for (int mt = 0; mt < 2; ++mt) {
        if (!TA) {
            const bf16* p = Ah + (wm + mt*16 + (lane & 15))*NT_STRIDE + ((lane >> 4) << 3);
            ldsm4(ah[mt], p);
            ldsm4(al[mt], p + (A_HALF_B/2));   // Al is A_HALF_B bytes after Ah
        } else {
            const bf16* p = Ah + (((lane >> 4) << 3) + (lane & 7))*TA_STRIDE + wm + mt*16 + (lane & 8);
            ldsm4t(ah[mt], p);
            ldsm4t(al[mt], p + (A_HALF_B/2));
        }
    }
    #pragma unroll
    for (int nt = 0; nt < 4; ++nt) {
        if (!TB) {
            const bf16* p = Bh + (wn + nt*8 + (lane & 7))*NT_STRIDE + (((lane >> 3) & 1) << 3);
            ldsm2(bh[nt], p);
            ldsm2(bl[nt], p + (B_HALF_B/2));
        } else {
            const bf16* p = Bh + (lane & 15)*TB_STRIDE + wn + nt*8;
            ldsm2t(bh[nt], p);
            ldsm2t(bl[nt], p + (B_HALF_B/2));
        }
    }
    #pragma unroll
    for (int mt = 0; mt < 2; ++mt)
        #pragma unroll
        for (int nt = 0; nt < 4; ++nt) {
            mma_bf16(acc[mt][nt], ah[mt], bh[nt]);
            mma_bf16(acc[mt][nt], ah[mt], bl[nt]);
            mma_bf16(acc[mt][nt], al[mt], bh[nt]);
        }
}

template<int TA, int TB>
__device__ __forceinline__ void gemm_core(Op A, Op B, int K, float acc[2][4][4],
                                          char (*sm)[STAGE_B], int tid) {
    const int lane = tid & 31, wid = tid >> 5;
    const int wm = (wid & 3) * 32, wn = (wid >> 2) * 32;
    const int KT = K >> 4;
    stage<TA,TB>(A, B, 0, sm[0], tid);
    cp_commit();
    for (int kt = 0; kt < KT; ++kt) {
        if (kt + 1 < KT) stage<TA,TB>(A, B, (kt+1) << 4, sm[(kt+1) & 1], tid);
        cp_commit();
        cp_wait1();
        __syncthreads();
        compute16<TA,TB>(sm[kt & 1], acc, lane, wm, wn);
        __syncthreads();
    }
}

#define GEMM_SMEM __shared__ __align__(16) char sm_[2][STAGE_B];

#define EPI_COORDS \
    const int lane = tid & 31, wid = tid >> 5; \
    const int gid = lane >> 2, tig = lane & 3; \
    const int wm = (wid & 3) * 32, wn = (wid >> 2) * 32;

#define EPI_LOOP(BODY) \
    _Pragma("unroll") for (int mt = 0; mt < 2; ++mt) \
    _Pragma("unroll") for (int nt = 0; nt < 4; ++nt) \
    _Pragma("unroll") for (int ci = 0; ci < 4; ++ci) { \
        int mr = wm + mt*16 + gid + ((ci >> 1) ? 8 : 0); \
        int nr = wn + nt*8 + tig*2 + (ci & 1); \
        float v = acc[mt][nt][ci]; \
        BODY \
    }

// ---------------- GEMM kernels ----------------
template<int WHICH>
__global__ void __launch_bounds__(256) tc_proj() {
    GEMM_SMEM;
    int tid = threadIdx.x;
    int m0 = blockIdx.y * 128, n0 = blockIdx.x * 64;
    float acc[2][4][4] = {};
    const bf16* wh = (WHICH==0) ? d_wqh : (WHICH==1) ? d_wkh : d_wvh;
    const bf16* wl = (WHICH==0) ? d_wql : (WHICH==1) ? d_wkl : d_wvl;
    Op A{d_hsh + (size_t)m0*DD, d_hsl + (size_t)m0*DD, DD};
    Op B{wh + (size_t)n0*DD, wl + (size_t)n0*DD, DD};
    gemm_core<0,0>(A, B, DD, acc, sm_, tid);
    EPI_COORDS;
    EPI_LOOP({
        size_t o = (size_t)(m0+mr)*DD + n0 + nr;
        if (WHICH < 2) {
            v = (v > 0.f) ? v + 1.f : expf(v);
            if (WHICH == 0) { d_sq[o] = v; wsplit(d_sqh, d_sql, o, v); }
            else            { d_sk[o] = v; wsplit(d_skh, d_skl, o, v); }
        } else wsplit(d_vh, d_vl, o, v);
    })
}

__global__ void __launch_bounds__(256) tc_memout() {
    GEMM_SMEM;
    int tid = threadIdx.x;
    int m0 = blockIdx.y * 128, n0 = blockIdx.x * 64;
    float acc[2][4][4] = {};
    Op A{d_sqh + (size_t)m0*DD, d_sql + (size_t)m0*DD, DD};
    Op B{d_memTh + (size_t)n0*DD, d_memTl + (size_t)n0*DD, DD};
    gemm_core<0,0>(A, B, DD, acc, sm_, tid);
    float act = d_scal[1];
    EPI_COORDS;
    EPI_LOOP({
        d_memout[(size_t)(m0+mr)*DD + n0 + nr] = v * act / d_normq[m0+mr];
    })
}

__global__ void __launch_bounds__(256) tc_kv() {
    GEMM_SMEM;
    int tid = threadIdx.x;
    int bn = blockIdx.z; int b = bn >> 4, n = bn & 15;
    size_t cb = (size_t)(b*SEQ + n*CH)*DD;
    int m0 = blockIdx.y * 128, n0 = blockIdx.x * 64;
    float acc[2][4][4] = {};
    Op A{d_skh + cb + m0, d_skl + cb + m0, DD};
    Op B{d_vh + cb + n0, d_vl + cb + n0, DD};
    gemm_core<1,1>(A, B, CH, acc, sm_, tid);
    float* C = d_G + (size_t)bn*DD*DD;
    EPI_COORDS;
    EPI_LOOP({
        C[(size_t)(m0+mr)*DD + n0 + nr] = v;
    })
}

__global__ void __launch_bounds__(256) tc_scores() {
    GEMM_SMEM;
    int tid = threadIdx.x;
    int bn = blockIdx.z; int b = bn >> 4, n = bn & 15;
    size_t cb = (size_t)(b*SEQ + n*CH)*DD;
    int n0 = blockIdx.x * 64;
    float acc[2][4][4] = {};
    Op A{d_sqh + cb, d_sql + cb, DD};
    Op B{d_skh + cb + (size_t)n0*DD, d_skl + cb + (size_t)n0*DD, DD};
    gemm_core<0,0>(A, B, DD, acc, sm_, tid);
    size_t co = (size_t)bn*CH*CH;
    EPI_COORDS;
    EPI_LOOP({
        int gj = n0 + nr;
        float m = (gj <= mr) ? v : 0.f;
        size_t o = co + (size_t)mr*CH + gj;
        d_Abuf[o] = m;
        wsplit(d_Abh, d_Abl, o, m);
    })
}

__global__ void __launch_bounds__(256) tc_attn() {
    GEMM_SMEM;
    int tid = threadIdx.x;
    int bn = blockIdx.z; int b = bn >> 4, n = bn & 15;
    size_t cb = (size_t)(b*SEQ + n*CH)*DD;
    int n0 = blockIdx.x * 64;
    float acc[2][4][4] = {};
    {
        Op A{d_sqh + cb, d_sql + cb, DD};
        Op B{d_Sph + (size_t)bn*DD*DD + n0, d_Spl + (size_t)bn*DD*DD + n0, DD};
        gemm_core<0,1>(A, B, DD, acc, sm_, tid);
    }
    {
        Op A{d_Abh + (size_t)bn*CH*CH, d_Abl + (size_t)bn*CH*CH, CH};
        Op B{d_vh + cb + n0, d_vl + cb + n0, DD};
        gemm_core<0,1>(A, B, CH, acc, sm_, tid);
    }
    EPI_COORDS;
    EPI_LOOP({
        d_local[cb + (size_t)mr*DD + n0 + nr] = v / d_den[bn*CH + mr];
    })
}

__global__ void __launch_bounds__(256) tc_final(float* __restrict__ Out) {
    GEMM_SMEM;
    int tid = threadIdx.x;
    int m0 = blockIdx.y * 128, n0 = blockIdx.x * 64;
    float acc[2][4][4] = {};
    Op A{d_cmh + (size_t)m0*DD, d_cml + (size_t)m0*DD, DD};
    Op B{d_woh + (size_t)n0*DD, d_wol + (size_t)n0*DD, DD};
    gemm_core<0,0>(A, B, DD, acc, sm_, tid);
    EPI_COORDS;
    EPI_LOOP({
        Out[(size_t)(m0+mr)*DD + n0 + nr] = v;
    })
}

// ---------------- launcher ----------------
extern "C" void kernel_launch(void* const* d_in, const int* in_sizes, int n_in,
                              void* d_out, int out_size) {
    const float* hs    = (const float*)d_in[0];
    const float* wq    = (const float*)d_in[1];
    const float* wk    = (const float*)d_in[2];
    const float* wv    = (const float*)d_in[3];
    const float* wo    = (const float*)d_in[4];
    const float* gate  = (const float*)d_in[5];
    const float* mem   = (const float*)d_in[6];
    const float* mnorm = (const float*)d_in[7];
    float* out = (float*)d_out;

    scalars_kernel<<<1, 1024>>>(gate, mnorm);

    // pre-split inputs to bf16 hi/lo
    bf16 *hsh, *hsl, *wqh, *wql, *wkh, *wkl, *wvh, *wvl, *woh, *wol;
    cudaGetSymbolAddress((void**)&hsh, d_hsh); cudaGetSymbolAddress((void**)&hsl, d_hsl);
    cudaGetSymbolAddress((void**)&wqh, d_wqh); cudaGetSymbolAddress((void**)&wql, d_wql);
    cudaGetSymbolAddress((void**)&wkh, d_wkh); cudaGetSymbolAddress((void**)&wkl, d_wkl);
    cudaGetSymbolAddress((void**)&wvh, d_wvh); cudaGetSymbolAddress((void**)&wvl, d_wvl);
    cudaGetSymbolAddress((void**)&woh, d_woh); cudaGetSymbolAddress((void**)&wol, d_wol);

    int n4hs = MTOT*DD/4, n4w = DD*DD/4;
    cvt_split_k<<<(n4hs+255)/256, 256>>>((const float4*)hs, (uint2*)hsh, (uint2*)hsl, n4hs);
    cvt_split_k<<<(n4w+255)/256, 256>>>((const float4*)wq, (uint2*)wqh, (uint2*)wql, n4w);
    cvt_split_k<<<(n4w+255)/256, 256>>>((const float4*)wk, (uint2*)wkh, (uint2*)wkl, n4w);
    cvt_split_k<<<(n4w+255)/256, 256>>>((const float4*)wv, (uint2*)wvh, (uint2*)wvl, n4w);
    cvt_split_k<<<(n4w+255)/256, 256>>>((const float4*)wo, (uint2*)woh, (uint2*)wol, n4w);
    cvt_T_k<<<(DD*DD+255)/256, 256>>>(mem);

    dim3 gP(DD/64, MTOT/128);           // (16, 32)
    tc_proj<0><<<gP, 256>>>();
    tc_proj<1><<<gP, 256>>>();
    tc_proj<2><<<gP, 256>>>();

    normq_kernel<<<(MTOT*32 + 255)/256, 256>>>(mnorm);
    tc_memout<<<gP, 256>>>();

    zc_kernel<<<(BSZ*NCH*DD + 255)/256, 256>>>();
    zprefix_kernel<<<(BSZ*DD + 255)/256, 256>>>();

    dim3 gKV(DD/64, DD/128, BSZ*NCH);   // (16, 8, 32)
    tc_kv<<<gKV, 256>>>();
    gprefix_kernel<<<(int)(((size_t)BSZ*DD*DD + 255)/256), 256>>>();

    dim3 gSc(CH/64, 1, BSZ*NCH);        // (2, 1, 32)
    tc_scores<<<gSc, 256>>>();
    den_kernel<<<(BSZ*NCH*CH*32 + 255)/256, 256>>>();

    dim3 gAt(DD/64, 1, BSZ*NCH);        // (16, 1, 32)
    tc_attn<<<gAt, 256>>>();

    combine_kernel<<<(MTOT*DD + 255)/256, 256>>>();
    tc_final<<<gP, 256>>>(out);
}

// round 5
// speedup vs baseline: 3.3616x; 1.0732x over previous
#include <cuda_runtime.h>
#include <cuda_bf16.h>
#include <math.h>
#include <stdint.h>

#define BSZ 2
#define SEQ 2048
#define DD 1024
#define CH 128
#define NCH 16
#define MTOT (BSZ*SEQ)        // 4096
#define EPSV 1e-6f

typedef __nv_bfloat16 bf16;

// ---------------- scratch ----------------
__device__ float d_sq[MTOT*DD];
__device__ float d_sk[MTOT*DD];
__device__ float d_memout[MTOT*DD];
__device__ float d_local[MTOT*DD];
__device__ float d_G[(size_t)BSZ*NCH*DD*DD];
__device__ float d_zz[BSZ*NCH*DD];
__device__ float d_Abuf[BSZ*NCH*CH*CH];
__device__ float d_den[BSZ*NCH*CH];
__device__ float d_normq[MTOT];
__device__ float d_scal[2];

__device__ bf16 d_hsh[MTOT*DD],  d_hsl[MTOT*DD];
__device__ bf16 d_wqh[DD*DD],    d_wql[DD*DD];
__device__ bf16 d_wkh[DD*DD],    d_wkl[DD*DD];
__device__ bf16 d_wvh[DD*DD],    d_wvl[DD*DD];
__device__ bf16 d_woh[DD*DD],    d_wol[DD*DD];
__device__ bf16 d_memTh[DD*DD],  d_memTl[DD*DD];
__device__ bf16 d_sqh[MTOT*DD],  d_sql[MTOT*DD];
__device__ bf16 d_skh[MTOT*DD],  d_skl[MTOT*DD];
__device__ bf16 d_vh [MTOT*DD],  d_vl [MTOT*DD];
__device__ bf16 d_Sph[(size_t)BSZ*NCH*DD*DD], d_Spl[(size_t)BSZ*NCH*DD*DD];
__device__ bf16 d_Abh[BSZ*NCH*CH*CH], d_Abl[BSZ*NCH*CH*CH];
__device__ bf16 d_cmh[MTOT*DD],  d_cml[MTOT*DD];

// ---------------- helpers ----------------
__device__ __forceinline__ void split1(float x, bf16& h, bf16& l) {
    h = __float2bfloat16(x);
    l = __float2bfloat16(x - __bfloat162float(h));
}
__device__ __forceinline__ void wsplit(bf16* H, bf16* L, size_t i, float v) {
    bf16 h, l; split1(v, h, l); H[i] = h; L[i] = l;
}

// ---------------- small kernels ----------------
__global__ void scalars_kernel(const float* __restrict__ gate,
                               const float* __restrict__ mnorm) {
    __shared__ float sh[1024];
    int t = threadIdx.x;
    sh[t] = mnorm[t];
    __syncthreads();
    for (int s = 512; s > 0; s >>= 1) { if (t < s) sh[t] += sh[t+s]; __syncthreads(); }
    if (t == 0) {
        d_scal[0] = 1.f / (1.f + expf(-gate[0]));
        d_scal[1] = (sh[0] >= EPSV) ? 1.f : 0.f;
    }
}

__global__ void cvt_split_k(const float4* __restrict__ src, uint2* __restrict__ hi,
                            uint2* __restrict__ lo, int n4) {
    int i = blockIdx.x * blockDim.x + threadIdx.x;
    if (i >= n4) return;
    float4 x = src[i];
    bf16 h0,h1,h2,h3,l0,l1,l2,l3;
    split1(x.x,h0,l0); split1(x.y,h1,l1); split1(x.z,h2,l2); split1(x.w,h3,l3);
    union { __nv_bfloat162 b[2]; uint2 u; } uh, ul;
    uh.b[0] = __halves2bfloat162(h0,h1); uh.b[1] = __halves2bfloat162(h2,h3);
    ul.b[0] = __halves2bfloat162(l0,l1); ul.b[1] = __halves2bfloat162(l2,l3);
    hi[i] = uh.u; lo[i] = ul.u;
}

__global__ void cvt_T_k(const float* __restrict__ src) {
    int idx = blockIdx.x * blockDim.x + threadIdx.x;
    if (idx >= DD*DD) return;
    int k = idx & (DD-1), n = idx >> 10;
    wsplit(d_memTh, d_memTl, (size_t)n*DD + k, src[(size_t)k*DD + n]);
}

__global__ void normq_kernel(const float* __restrict__ mnorm) {
    int warp = (blockIdx.x * blockDim.x + threadIdx.x) >> 5;
    int lane = threadIdx.x & 31;
    if (warp >= MTOT) return;
    const float* row = d_sq + (size_t)warp * DD;
    float s = 0.f;
    for (int k = lane; k < DD; k += 32) s += row[k] * mnorm[k];
    #pragma unroll
    for (int o = 16; o > 0; o >>= 1) s += __shfl_xor_sync(0xffffffffu, s, o);
    if (lane == 0) d_normq[warp] = fmaxf(s, EPSV);
}

__global__ void zc_kernel() {
    int idx = blockIdx.x * blockDim.x + threadIdx.x;
    if (idx >= BSZ*NCH*DD) return;
    int d = idx % DD; int bn = idx / DD;
    int b = bn >> 4, n = bn & 15;
    const float* base = d_sk + (size_t)(b*SEQ + n*CH)*DD + d;
    float s = 0.f;
    #pragma unroll 4
    for (int i = 0; i < CH; ++i) s += base[(size_t)i*DD];
    d_zz[idx] = s;
}

__global__ void zprefix_kernel() {
    int idx = blockIdx.x * blockDim.x + threadIdx.x;
    if (idx >= BSZ*DD) return;
    int b = idx / DD, d = idx % DD;
    float run = 0.f;
    for (int n = 0; n < NCH; ++n) {
        float* p = d_zz + (size_t)(b*NCH + n)*DD + d;
        float t = *p; *p = run; run += t;
    }
}

__global__ void gprefix_kernel() {
    size_t idx = (size_t)blockIdx.x * blockDim.x + threadIdx.x;
    if (idx >= (size_t)BSZ*DD*DD) return;
    int b = (int)(idx / ((size_t)DD*DD));
    size_t rem = idx % ((size_t)DD*DD);
    float run = 0.f;
    for (int n = 0; n < NCH; ++n) {
        size_t off = ((size_t)(b*NCH + n)*DD*DD) + rem;
        float t = d_G[off];
        wsplit(d_Sph, d_Spl, off, run);
        run += t;
    }
}

__global__ void den_kernel() {
    int warp = (blockIdx.x * blockDim.x + threadIdx.x) >> 5;
    int lane = threadIdx.x & 31;
    if (warp >= BSZ*NCH*CH) return;
    int bn = warp / CH, i = warp % CH;
    int b = bn >> 4, n = bn & 15;
    const float* qr = d_sq + (size_t)(b*SEQ + n*CH + i)*DD;
    const float* zr = d_zz + (size_t)bn*DD;
    float s = 0.f;
    for (int k = lane; k < DD; k += 32) s += qr[k] * zr[k];
    const float* ar = d_Abuf + (size_t)bn*CH*CH + (size_t)i*CH;
    for (int j = lane; j < CH; j += 32) s += ar[j];
    #pragma unroll
    for (int o = 16; o > 0; o >>= 1) s += __shfl_xor_sync(0xffffffffu, s, o);
    if (lane == 0) d_den[warp] = fmaxf(s, EPSV);
}

__global__ void combine_kernel() {
    size_t i = ((size_t)blockIdx.x * blockDim.x + threadIdx.x);
    if (i >= (size_t)MTOT*DD) return;
    float g = d_scal[0], og = 1.f - g;
    wsplit(d_cmh, d_cml, i, g * d_memout[i] + og * d_local[i]);
}

// ---------------- tensor-core GEMM core ----------------
// Block 128x128, K-step 32, 256 thr = 8 warps (4M x 2N), warp tile 32x64.
// bf16x3: C += Ah*Bh + Ah*Bl + Al*Bh. 2-stage cp.async pipeline, dynamic smem.

#define NT_STRIDE 40      // [rows][32 k + 8 pad]
#define T_STRIDE 136      // [32 k][128 + 8 pad]
#define A_HALF_B 10240    // bytes: max(128*40, 32*136)*2
#define B_HALF_B 10240
#define STAGE_B (2*A_HALF_B + 2*B_HALF_B)   // 40960
#define SMEM_TOT (2*STAGE_B)                 // 81920

__device__ __forceinline__ void cpa16(void* dst, const void* src) {
    uint32_t d = (uint32_t)__cvta_generic_to_shared(dst);
    asm volatile("cp.async.cg.shared.global [%0], [%1], 16;" :: "r"(d), "l"(src));
}
__device__ __forceinline__ void cp_commit() { asm volatile("cp.async.commit_group;"); }
__device__ __forceinline__ void cp_wait1()  { asm volatile("cp.async.wait_group 1;"); }

__device__ __forceinline__ void ldsm4(uint32_t* r, const bf16* p) {
    uint32_t a = (uint32_t)__cvta_generic_to_shared(p);
    asm volatile("ldmatrix.sync.aligned.m8n8.x4.shared.b16 {%0,%1,%2,%3}, [%4];"
        : "=r"(r[0]), "=r"(r[1]), "=r"(r[2]), "=r"(r[3]) : "r"(a));
}
__device__ __forceinline__ void ldsm4t(uint32_t* r, const bf16* p) {
    uint32_t a = (uint32_t)__cvta_generic_to_shared(p);
    asm volatile("ldmatrix.sync.aligned.m8n8.x4.trans.shared.b16 {%0,%1,%2,%3}, [%4];"
        : "=r"(r[0]), "=r"(r[1]), "=r"(r[2]), "=r"(r[3]) : "r"(a));
}
__device__ __forceinline__ void mma_bf16(float* c, const uint32_t* a, const uint32_t* b) {
    asm volatile("mma.sync.aligned.m16n8k16.row.col.f32.bf16.bf16.f32 "
        "{%0,%1,%2,%3}, {%4,%5,%6,%7}, {%8,%9}, {%0,%1,%2,%3};"
        : "+f"(c[0]), "+f"(c[1]), "+f"(c[2]), "+f"(c[3])
        : "r"(a[0]), "r"(a[1]), "r"(a[2]), "r"(a[3]), "r"(b[0]), "r"(b[1]));
}

struct Op { const bf16 *h, *l; int ld; };

template<int TA, int TB>
__device__ __forceinline__ void stage(Op A, Op B, int k0, char* sm, int tid) {
    bf16* Ah = (bf16*)sm;
    bf16* Al = (bf16*)(sm + A_HALF_B);
    bf16* Bh = (bf16*)(sm + 2*A_HALF_B);
    bf16* Bl = (bf16*)(sm + 2*A_HALF_B + B_HALF_B);
    #pragma unroll
    for (int i = 0; i < 2; ++i) {
        int idx = tid + 256*i;
        if (!TA) {
            int row = idx >> 2, ch = idx & 3;
            size_t so = (size_t)row * A.ld + k0 + ch*8;
            cpa16(Ah + row*NT_STRIDE + ch*8, A.h + so);
            cpa16(Al + row*NT_STRIDE + ch*8, A.l + so);
        } else {
            int row = idx >> 4, ch = idx & 15;
            size_t so = (size_t)(k0 + row) * A.ld + ch*8;
            cpa16(Ah + row*T_STRIDE + ch*8, A.h + so);
            cpa16(Al + row*T_STRIDE + ch*8, A.l + so);
        }
        if (!TB) {
            int row = idx >> 2, ch = idx & 3;
            size_t so = (size_t)row * B.ld + k0 + ch*8;
            cpa16(Bh + row*NT_STRIDE + ch*8, B.h + so);
            cpa16(Bl + row*NT_STRIDE + ch*8, B.l + so);
        } else {
            int row = idx >> 4, ch = idx & 15;
            size_t so = (size_t)(k0 + row) * B.ld + ch*8;
            cpa16(Bh + row*T_STRIDE + ch*8, B.h + so);
            cpa16(Bl + row*T_STRIDE + ch*8, B.l + so);
        }
    }
}

template<int TA, int TB>
__device__ __forceinline__ void compute16(char* sm, int ks, float acc[2][8][4],
                                          int lane, int wm, int wn) {
    bf16* Ah = (bf16*)sm;
    bf16* Bh = (bf16*)(sm + 2*A_HALF_B);
    const int AHE = A_HALF_B/2, BHE = B_HALF_B/2;  // element offsets hi->lo
    uint32_t ah[2][4], al[2][4], bh[8][2], bl[8][2];
    #pragma unroll
    for (int mt = 0; mt < 2; ++mt) {
        if (!TA) {
            const bf16* p = Ah + (wm + mt*16 + (lane & 15))*NT_STRIDE + ks + ((lane >> 4) << 3);
            ldsm4(ah[mt], p);
            ldsm4(al[mt], p + AHE);
        } else {
            const bf16* p = Ah + (ks + ((lane >> 4) << 3) + (lane & 7))*T_STRIDE + wm + mt*16 + (lane & 8);
            ldsm4t(ah[mt], p);
            ldsm4t(al[mt], p + AHE);
        }
    }
    #pragma unroll
    for (int nq = 0; nq < 4; ++nq) {
        uint32_t r[4], s[4];
        if (!TB) {
            const bf16* p = Bh + (wn + nq*16 + (lane & 15))*NT_STRIDE + ks + ((lane >> 4) << 3);
            ldsm4(r, p);
            ldsm4(s, p + BHE);
            bh[2*nq][0]=r[0]; bh[2*nq][1]=r[2]; bh[2*nq+1][0]=r[1]; bh[2*nq+1][1]=r[3];
            bl[2*nq][0]=s[0]; bl[2*nq][1]=s[2]; bl[2*nq+1][0]=s[1]; bl[2*nq+1][1]=s[3];
        } else {
            const bf16* p = Bh + (ks + (lane & 15))*T_STRIDE + wn + nq*16 + ((lane >> 4) << 3);
            ldsm4t(r, p);
            ldsm4t(s, p + BHE);
            bh[2*nq][0]=r[0]; bh[2*nq][1]=r[1]; bh[2*nq+1][0]=r[2]; bh[2*nq+1][1]=r[3];
            bl[2*nq][0]=s[0]; bl[2*nq][1]=s[1]; bl[2*nq+1][0]=s[2]; bl[2*nq+1][1]=s[3];
        }
    }
    #pragma unroll
    for (int mt = 0; mt < 2; ++mt)
        #pragma unroll
        for (int nt = 0; nt < 8; ++nt) {
            mma_bf16(acc[mt][nt], ah[mt], bh[nt]);
            mma_bf16(acc[mt][nt], ah[mt], bl[nt]);
            mma_bf16(acc[mt][nt], al[mt], bh[nt]);
        }
}

template<int TA, int TB>
__device__ __forceinline__ void gemm_core(Op A, Op B, int K, float acc[2][8][4],
                                          char* smbase, int tid) {
    const int lane = tid & 31, wid = tid >> 5;
    const int wm = (wid & 3) * 32, wn = (wid >> 2) * 64;
    const int KT = K >> 5;
    stage<TA,TB>(A, B, 0, smbase, tid);
    cp_commit();
    for (int kt = 0; kt < KT; ++kt) {
        if (kt + 1 < KT) stage<TA,TB>(A, B, (kt+1) << 5, smbase + ((kt+1) & 1)*STAGE_B, tid);
        cp_commit();
        cp_wait1();
        __syncthreads();
        char* cur = smbase + (kt & 1)*STAGE_B;
        compute16<TA,TB>(cur, 0,  acc, lane, wm, wn);
        compute16<TA,TB>(cur, 16, acc, lane, wm, wn);
        __syncthreads();
    }
}

#define GEMM_SMEM extern __shared__ char sm_[];

#define EPI_COORDS \
    const int lane = tid & 31, wid = tid >> 5; \
    const int gid = lane >> 2, tig = lane & 3; \
    const int wm = (wid & 3) * 32, wn = (wid >> 2) * 64;

#define EPI_LOOP(BODY) \
    _Pragma("unroll") for (int mt = 0; mt < 2; ++mt) \
    _Pragma("unroll") for (int nt = 0; nt < 8; ++nt) \
    _Pragma("unroll") for (int ci = 0; ci < 4; ++ci) { \
        int mr = wm + mt*16 + gid + ((ci >> 1) ? 8 : 0); \
        int nr = wn + nt*8 + tig*2 + (ci & 1); \
        float v = acc[mt][nt][ci]; \
        BODY \
    }

// ---------------- GEMM kernels ----------------
__global__ void __launch_bounds__(256, 1) tc_proj3() {
    GEMM_SMEM;
    int tid = threadIdx.x;
    int m0 = blockIdx.y * 128, n0 = blockIdx.x * 128;
    int which = blockIdx.z;
    const bf16* wh = (which==0) ? d_wqh : (which==1) ? d_wkh : d_wvh;
    const bf16* wl = (which==0) ? d_wql : (which==1) ? d_wkl : d_wvl;
    float acc[2][8][4] = {};
    Op A{d_hsh + (size_t)m0*DD, d_hsl + (size_t)m0*DD, DD};
    Op B{wh + (size_t)n0*DD, wl + (size_t)n0*DD, DD};
    gemm_core<0,0>(A, B, DD, acc, sm_, tid);
    EPI_COORDS;
    if (which == 0) {
        EPI_LOOP({
            size_t o = (size_t)(m0+mr)*DD + n0 + nr;
            v = (v > 0.f) ? v + 1.f : expf(v);
            d_sq[o] = v; wsplit(d_sqh, d_sql, o, v);
        })
    } else if (which == 1) {
        EPI_LOOP({
            size_t o = (size_t)(m0+mr)*DD + n0 + nr;
            v = (v > 0.f) ? v + 1.f : expf(v);
            d_sk[o] = v; wsplit(d_skh, d_skl, o, v);
        })
    } else {
        EPI_LOOP({
            size_t o = (size_t)(m0+mr)*DD + n0 + nr;
            wsplit(d_vh, d_vl, o, v);
        })
    }
}

__global__ void __launch_bounds__(256, 1) tc_memout() {
    GEMM_SMEM;
    int tid = threadIdx.x;
    int m0 = blockIdx.y * 128, n0 = blockIdx.x * 128;
    float acc[2][8][4] = {};
    Op A{d_sqh + (size_t)m0*DD, d_sql + (size_t)m0*DD, DD};
    Op B{d_memTh + (size_t)n0*DD, d_memTl + (size_t)n0*DD, DD};
    gemm_core<0,0>(A, B, DD, acc, sm_, tid);
    float act = d_scal[1];
    EPI_COORDS;
    EPI_LOOP({
        d_memout[(size_t)(m0+mr)*DD + n0 + nr] = v * act / d_normq[m0+mr];
    })
}

__global__ void __launch_bounds__(256, 1) tc_kv() {
    GEMM_SMEM;
    int tid = threadIdx.x;
    int bn = blockIdx.z; int b = bn >> 4, n = bn & 15;
    size_t cb = (size_t)(b*SEQ + n*CH)*DD;
    int m0 = blockIdx.y * 128, n0 = blockIdx.x * 128;
    float acc[2][8][4] = {};
    Op A{d_skh + cb + m0, d_skl + cb + m0, DD};
    Op B{d_vh + cb + n0, d_vl + cb + n0, DD};
    gemm_core<1,1>(A, B, CH, acc, sm_, tid);
    float* C = d_G + (size_t)bn*DD*DD;
    EPI_COORDS;
    EPI_LOOP({
        C[(size_t)(m0+mr)*DD + n0 + nr] = v;
    })
}

__global__ void __launch_bounds__(256, 1) tc_scores() {
    GEMM_SMEM;
    int tid = threadIdx.x;
    int bn = blockIdx.z; int b = bn >> 4, n = bn & 15;
    size_t cb = (size_t)(b*SEQ + n*CH)*DD;
    float acc[2][8][4] = {};
    Op A{d_sqh + cb, d_sql + cb, DD};
    Op B{d_skh + cb, d_skl + cb, DD};
    gemm_core<0,0>(A, B, DD, acc, sm_, tid);
    size_t co = (size_t)bn*CH*CH;
    EPI_COORDS;
    EPI_LOOP({
        float m = (nr <= mr) ? v : 0.f;
        size_t o = co + (size_t)mr*CH + nr;
        d_Abuf[o] = m;
        wsplit(d_Abh, d_Abl, o, m);
    })
}

__global__ void __launch_bounds__(256, 1) tc_attn() {
    GEMM_SMEM;
    int tid = threadIdx.x;
    int bn = blockIdx.z; int b = bn >> 4, n = bn & 15;
    size_t cb = (size_t)(b*SEQ + n*CH)*DD;
    int n0 = blockIdx.x * 128;
    float acc[2][8][4] = {};
    {
        Op A{d_sqh + cb, d_sql + cb, DD};
        Op B{d_Sph + (size_t)bn*DD*DD + n0, d_Spl + (size_t)bn*DD*DD + n0, DD};
        gemm_core<0,1>(A, B, DD, acc, sm_, tid);
    }
    {
        Op A{d_Abh + (size_t)bn*CH*CH, d_Abl + (size_t)bn*CH*CH, CH};
        Op B{d_vh + cb + n0, d_vl + cb + n0, DD};
        gemm_core<0,1>(A, B, CH, acc, sm_, tid);
    }
    EPI_COORDS;
    EPI_LOOP({
        d_local[cb + (size_t)mr*DD + n0 + nr] = v / d_den[bn*CH + mr];
    })
}

__global__ void __launch_bounds__(256, 1) tc_final(float* __restrict__ Out) {
    GEMM_SMEM;
    int tid = threadIdx.x;
    int m0 = blockIdx.y * 128, n0 = blockIdx.x * 128;
    float acc[2][8][4] = {};
    Op A{d_cmh + (size_t)m0*DD, d_cml + (size_t)m0*DD, DD};
    Op B{d_woh + (size_t)n0*DD, d_wol + (size_t)n0*DD, DD};
    gemm_core<0,0>(A, B, DD, acc, sm_, tid);
    EPI_COORDS;
    EPI_LOOP({
        Out[(size_t)(m0+mr)*DD + n0 + nr] = v;
    })
}

// ---------------- launcher ----------------
extern "C" void kernel_launch(void* const* d_in, const int* in_sizes, int n_in,
                              void* d_out, int out_size) {
    const float* hs    = (const float*)d_in[0];
    const float* wq    = (const float*)d_in[1];
    const float* wk    = (const float*)d_in[2];
    const float* wv    = (const float*)d_in[3];
    const float* wo    = (const float*)d_in[4];
    const float* gate  = (const float*)d_in[5];
    const float* mem   = (const float*)d_in[6];
    const float* mnorm = (const float*)d_in[7];
    float* out = (float*)d_out;

    cudaFuncSetAttribute(tc_proj3,  cudaFuncAttributeMaxDynamicSharedMemorySize, SMEM_TOT);
    cudaFuncSetAttribute(tc_memout, cudaFuncAttributeMaxDynamicSharedMemorySize, SMEM_TOT);
    cudaFuncSetAttribute(tc_kv,     cudaFuncAttributeMaxDynamicSharedMemorySize, SMEM_TOT);
    cudaFuncSetAttribute(tc_scores, cudaFuncAttributeMaxDynamicSharedMemorySize, SMEM_TOT);
    cudaFuncSetAttribute(tc_attn,   cudaFuncAttributeMaxDynamicSharedMemorySize, SMEM_TOT);
    cudaFuncSetAttribute(tc_final,  cudaFuncAttributeMaxDynamicSharedMemorySize, SMEM_TOT);

    scalars_kernel<<<1, 1024>>>(gate, mnorm);

    bf16 *hsh, *hsl, *wqh, *wql, *wkh, *wkl, *wvh, *wvl, *woh, *wol;
    cudaGetSymbolAddress((void**)&hsh, d_hsh); cudaGetSymbolAddress((void**)&hsl, d_hsl);
    cudaGetSymbolAddress((void**)&wqh, d_wqh); cudaGetSymbolAddress((void**)&wql, d_wql);
    cudaGetSymbolAddress((void**)&wkh, d_wkh); cudaGetSymbolAddress((void**)&wkl, d_wkl);
    cudaGetSymbolAddress((void**)&wvh, d_wvh); cudaGetSymbolAddress((void**)&wvl, d_wvl);
    cudaGetSymbolAddress((void**)&woh, d_woh); cudaGetSymbolAddress((void**)&wol, d_wol);

    int n4hs = MTOT*DD/4, n4w = DD*DD/4;
    cvt_split_k<<<(n4hs+255)/256, 256>>>((const float4*)hs, (uint2*)hsh, (uint2*)hsl, n4hs);
    cvt_split_k<<<(n4w+255)/256, 256>>>((const float4*)wq, (uint2*)wqh, (uint2*)wql, n4w);
    cvt_split_k<<<(n4w+255)/256, 256>>>((const float4*)wk, (uint2*)wkh, (uint2*)wkl, n4w);
    cvt_split_k<<<(n4w+255)/256, 256>>>((const float4*)wv, (uint2*)wvh, (uint2*)wvl, n4w);
    cvt_split_k<<<(n4w+255)/256, 256>>>((const float4*)wo, (uint2*)woh, (uint2*)wol, n4w);
    cvt_T_k<<<(DD*DD+255)/256, 256>>>(mem);

    dim3 gP(DD/128, MTOT/128, 3);       // (8, 32, 3)
    tc_proj3<<<gP, 256, SMEM_TOT>>>();

    normq_kernel<<<(MTOT*32 + 255)/256, 256>>>(mnorm);
    dim3 gM(DD/128, MTOT/128);          // (8, 32)
    tc_memout<<<gM, 256, SMEM_TOT>>>();

    zc_kernel<<<(BSZ*NCH*DD + 255)/256, 256>>>();
    zprefix_kernel<<<(BSZ*DD + 255)/256, 256>>>();

    dim3 gKV(DD/128, DD/128, BSZ*NCH);  // (8, 8, 32)
    tc_kv<<<gKV, 256, SMEM_TOT>>>();
    gprefix_kernel<<<(int)(((size_t)BSZ*DD*DD + 255)/256), 256>>>();

    dim3 gSc(1, 1, BSZ*NCH);            // (1, 1, 32)
    tc_scores<<<gSc, 256, SMEM_TOT>>>();
    den_kernel<<<(BSZ*NCH*CH*32 + 255)/256, 256>>>();

    dim3 gAt(DD/128, 1, BSZ*NCH);       // (8, 1, 32)
    tc_attn<<<gAt, 256, SMEM_TOT>>>();

    combine_kernel<<<(MTOT*DD + 255)/256, 256>>>();
    tc_final<<<gM, 256, SMEM_TOT>>>(out);
}

// round 7
// speedup vs baseline: 4.8829x; 1.4525x over previous
#include <cuda_runtime.h>
#include <cuda_fp16.h>
#include <math.h>
#include <stdint.h>

#define BSZ 2
#define SEQ 2048
#define DD 1024
#define CH 128
#define NCH 16
#define MTOT (BSZ*SEQ)        // 4096
#define EPSV 1e-6f

typedef __half hf;

// ---------------- scratch ----------------
__device__ float d_sq[MTOT*DD];
__device__ float d_sk[MTOT*DD];
__device__ float d_memout[MTOT*DD];
__device__ float d_local[MTOT*DD];
__device__ float d_G[(size_t)BSZ*NCH*DD*DD];     // G[bn][d][e] fp32
__device__ float d_zz[BSZ*NCH*DD];
__device__ float d_Abuf[BSZ*NCH*CH*CH];
__device__ float d_den[BSZ*NCH*CH];
__device__ float d_normq[MTOT];
__device__ float d_scal[2];

// fp16 operand buffers. A-side-only matrices have hi only; B-side need hi+lo.
__device__ hf d_hsh[MTOT*DD];
__device__ hf d_wqh[DD*DD],    d_wql[DD*DD];
__device__ hf d_wkh[DD*DD],    d_wkl[DD*DD];
__device__ hf d_wvh[DD*DD],    d_wvl[DD*DD];
__device__ hf d_woh[DD*DD],    d_wol[DD*DD];
__device__ hf d_memTh[DD*DD],  d_memTl[DD*DD];   // memory transposed [N][K]
__device__ hf d_sqh[MTOT*DD];                    // A-only
__device__ hf d_skh[MTOT*DD],  d_skl[MTOT*DD];   // A (kv) and B (scores)
__device__ hf d_vh [MTOT*DD],  d_vl [MTOT*DD];   // B
__device__ hf d_Sph[(size_t)BSZ*NCH*DD*DD], d_Spl[(size_t)BSZ*NCH*DD*DD]; // B
__device__ hf d_Abh[BSZ*NCH*CH*CH];              // A-only
__device__ hf d_cmh[MTOT*DD];                    // A-only

// ---------------- helpers ----------------
__device__ __forceinline__ void split1(float x, hf& h, hf& l) {
    h = __float2half_rn(x);
    l = __float2half_rn(x - __half2float(h));
}
__device__ __forceinline__ void wsplit(hf* H, hf* L, size_t i, float v) {
    hf h, l; split1(v, h, l); H[i] = h; L[i] = l;
}

// ---------------- small kernels ----------------
__global__ void scalars_kernel(const float* __restrict__ gate,
                               const float* __restrict__ mnorm) {
    __shared__ float sh[1024];
    int t = threadIdx.x;
    sh[t] = mnorm[t];
    __syncthreads();
    for (int s = 512; s > 0; s >>= 1) { if (t < s) sh[t] += sh[t+s]; __syncthreads(); }
    if (t == 0) {
        d_scal[0] = 1.f / (1.f + expf(-gate[0]));
        d_scal[1] = (sh[0] >= EPSV) ? 1.f : 0.f;
    }
}

__global__ void cvt_split_k(const float4* __restrict__ src, uint2* __restrict__ hi,
                            uint2* __restrict__ lo, int n4) {
    int i = blockIdx.x * blockDim.x + threadIdx.x;
    if (i >= n4) return;
    float4 x = src[i];
    hf h0,h1,h2,h3,l0,l1,l2,l3;
    split1(x.x,h0,l0); split1(x.y,h1,l1); split1(x.z,h2,l2); split1(x.w,h3,l3);
    union { __half2 b[2]; uint2 u; } uh, ul;
    uh.b[0] = __halves2half2(h0,h1); uh.b[1] = __halves2half2(h2,h3);
    ul.b[0] = __halves2half2(l0,l1); ul.b[1] = __halves2half2(l2,l3);
    hi[i] = uh.u; lo[i] = ul.u;
}

__global__ void cvt_hi_k(const float4* __restrict__ src, uint2* __restrict__ hi, int n4) {
    int i = blockIdx.x * blockDim.x + threadIdx.x;
    if (i >= n4) return;
    float4 x = src[i];
    union { __half2 b[2]; uint2 u; } uh;
    uh.b[0] = __halves2half2(__float2half_rn(x.x), __float2half_rn(x.y));
    uh.b[1] = __halves2half2(__float2half_rn(x.z), __float2half_rn(x.w));
    hi[i] = uh.u;
}

__global__ void cvt_T_k(const float* __restrict__ src) {
    int idx = blockIdx.x * blockDim.x + threadIdx.x;
    if (idx >= DD*DD) return;
    int k = idx & (DD-1), n = idx >> 10;
    wsplit(d_memTh, d_memTl, (size_t)n*DD + k, src[(size_t)k*DD + n]);
}

__global__ void normq_kernel(const float* __restrict__ mnorm) {
    int warp = (blockIdx.x * blockDim.x + threadIdx.x) >> 5;
    int lane = threadIdx.x & 31;
    if (warp >= MTOT) return;
    const float* row = d_sq + (size_t)warp * DD;
    float s = 0.f;
    for (int k = lane; k < DD; k += 32) s += row[k] * mnorm[k];
    #pragma unroll
    for (int o = 16; o > 0; o >>= 1) s += __shfl_xor_sync(0xffffffffu, s, o);
    if (lane == 0) d_normq[warp] = fmaxf(s, EPSV);
}

__global__ void zc_kernel() {
    int idx = blockIdx.x * blockDim.x + threadIdx.x;
    if (idx >= BSZ*NCH*DD) return;
    int d = idx % DD; int bn = idx / DD;
    int b = bn >> 4, n = bn & 15;
    const float* base = d_sk + (size_t)(b*SEQ + n*CH)*DD + d;
    float s = 0.f;
    #pragma unroll 4
    for (int i = 0; i < CH; ++i) s += base[(size_t)i*DD];
    d_zz[idx] = s;
}

__global__ void zprefix_kernel() {
    int idx = blockIdx.x * blockDim.x + threadIdx.x;
    if (idx >= BSZ*DD) return;
    int b = idx / DD, d = idx % DD;
    float run = 0.f;
    for (int n = 0; n < NCH; ++n) {
        float* p = d_zz + (size_t)(b*NCH + n)*DD + d;
        float t = *p; *p = run; run += t;
    }
}

// exclusive prefix of G over chunks -> Sp hi/lo fp16 (layout preserved [d][e])
__global__ void gprefix_kernel() {
    size_t idx = (size_t)blockIdx.x * blockDim.x + threadIdx.x;
    if (idx >= (size_t)BSZ*DD*DD) return;
    int b = (int)(idx / ((size_t)DD*DD));
    size_t rem = idx % ((size_t)DD*DD);
    float run = 0.f;
    for (int n = 0; n < NCH; ++n) {
        size_t off = ((size_t)(b*NCH + n)*DD*DD) + rem;
        float t = d_G[off];
        wsplit(d_Sph, d_Spl, off, run);
        run += t;
    }
}

__global__ void den_kernel() {
    int warp = (blockIdx.x * blockDim.x + threadIdx.x) >> 5;
    int lane = threadIdx.x & 31;
    if (warp >= BSZ*NCH*CH) return;
    int bn = warp / CH, i = warp % CH;
    int b = bn >> 4, n = bn & 15;
    const float* qr = d_sq + (size_t)(b*SEQ + n*CH + i)*DD;
    const float* zr = d_zz + (size_t)bn*DD;
    float s = 0.f;
    for (int k = lane; k < DD; k += 32) s += qr[k] * zr[k];
    const float* ar = d_Abuf + (size_t)bn*CH*CH + (size_t)i*CH;
    for (int j = lane; j < CH; j += 32) s += ar[j];
    #pragma unroll
    for (int o = 16; o > 0; o >>= 1) s += __shfl_xor_sync(0xffffffffu, s, o);
    if (lane == 0) d_den[warp] = fmaxf(s, EPSV);
}

__global__ void combine_kernel() {
    size_t i = ((size_t)blockIdx.x * blockDim.x + threadIdx.x);
    if (i >= (size_t)MTOT*DD) return;
    float g = d_scal[0], og = 1.f - g;
    d_cmh[i] = __float2half_rn(g * d_memout[i] + og * d_local[i]);
}

// ---------------- tensor-core GEMM core (fp16 x2 split) ----------------
// Block 128x128, K-step 32, 256 thr = 8 warps (4M x 2N), warp tile 32x64.
// D = Ah*Bh + Ah*Bl (A truncated to fp16-hi, err ~2^-11).
// 2-stage cp.async pipeline, dynamic smem, 3 staged matrices per step.

#define NT_STRIDE 40      // [rows][32 k + 8 pad] halfs
#define T_STRIDE 136      // [32 k][128 + 8 pad] halfs
#define MAT_B 10240       // bytes per staged matrix: max(128*40, 32*136)*2
#define STAGE_B (3*MAT_B)            // 30720: Ah, Bh, Bl
#define SMEM_TOT (2*STAGE_B)         // 61440

__device__ __forceinline__ void cpa16(void* dst, const void* src) {
    uint32_t d = (uint32_t)__cvta_generic_to_shared(dst);
    asm volatile("cp.async.cg.shared.global [%0], [%1], 16;" :: "r"(d), "l"(src));
}
__device__ __forceinline__ void cp_commit() { asm volatile("cp.async.commit_group;"); }
__device__ __forceinline__ void cp_wait1()  { asm volatile("cp.async.wait_group 1;"); }

__device__ __forceinline__ void ldsm4(uint32_t* r, const hf* p) {
    uint32_t a = (uint32_t)__cvta_generic_to_shared(p);
    asm volatile("ldmatrix.sync.aligned.m8n8.x4.shared.b16 {%0,%1,%2,%3}, [%4];"
        : "=r"(r[0]), "=r"(r[1]), "=r"(r[2]), "=r"(r[3]) : "r"(a));
}
__device__ __forceinline__ void ldsm4t(uint32_t* r, const hf* p) {
    uint32_t a = (uint32_t)__cvta_generic_to_shared(p);
    asm volatile("ldmatrix.sync.aligned.m8n8.x4.trans.shared.b16 {%0,%1,%2,%3}, [%4];"
        : "=r"(r[0]), "=r"(r[1]), "=r"(r[2]), "=r"(r[3]) : "r"(a));
}
__device__ __forceinline__ void mma_f16(float* c, const uint32_t* a, const uint32_t* b) {
    asm volatile("mma.sync.aligned.m16n8k16.row.col.f32.f16.f16.f32 "
        "{%0,%1,%2,%3}, {%4,%5,%6,%7}, {%8,%9}, {%0,%1,%2,%3};"
        : "+f"(c[0]), "+f"(c[1]), "+f"(c[2]), "+f"(c[3])
        : "r"(a[0]), "r"(a[1]), "r"(a[2]), "r"(a[3]), "r"(b[0]), "r"(b[1]));
}

struct OpA { const hf* h; int ld; };
struct OpB { const hf *h, *l; int ld; };

template<int TA, int TB>
__device__ __forceinline__ void stage(OpA A, OpB B, int k0, char* sm, int tid) {
    hf* Ah = (hf*)sm;
    hf* Bh = (hf*)(sm + MAT_B);
    hf* Bl = (hf*)(sm + 2*MAT_B);
    #pragma unroll
    for (int i = 0; i < 2; ++i) {
        int idx = tid + 256*i;            // 512 16B-chunks per matrix
        if (!TA) {
            int row = idx >> 2, ch = idx & 3;
            cpa16(Ah + row*NT_STRIDE + ch*8, A.h + (size_t)row*A.ld + k0 + ch*8);
        } else {
            int row = idx >> 4, ch = idx & 15;
            cpa16(Ah + row*T_STRIDE + ch*8, A.h + (size_t)(k0 + row)*A.ld + ch*8);
        }
        if (!TB) {
            int row = idx >> 2, ch = idx & 3;
            size_t so = (size_t)row * B.ld + k0 + ch*8;
            cpa16(Bh + row*NT_STRIDE + ch*8, B.h + so);
            cpa16(Bl + row*NT_STRIDE + ch*8, B.l + so);
        } else {
            int row = idx >> 4, ch = idx & 15;
            size_t so = (size_t)(k0 + row) * B.ld + ch*8;
            cpa16(Bh + row*T_STRIDE + ch*8, B.h + so);
            cpa16(Bl + row*T_STRIDE + ch*8, B.l + so);
        }
    }
}

template<int TA, int TB>
__device__ __forceinline__ void compute16(char* sm, int ks, float acc[2][8][4],
                                          int lane, int wm, int wn) {
    hf* Ah = (hf*)sm;
    hf* Bh = (hf*)(sm + MAT_B);
    const int BHE = MAT_B/2;   // element offset Bh -> Bl
    uint32_t ah[2][4], bh[8][2], bl[8][2];
    #pragma unroll
    for (int mt = 0; mt < 2; ++mt) {
        if (!TA) {
            const hf* p = Ah + (wm + mt*16 + (lane & 15))*NT_STRIDE + ks + ((lane >> 4) << 3);
            ldsm4(ah[mt], p);
        } else {
            const hf* p = Ah + (ks + ((lane >> 4) << 3) + (lane & 7))*T_STRIDE + wm + mt*16 + (lane & 8);
            ldsm4t(ah[mt], p);
        }
    }
    #pragma unroll
    for (int nq = 0; nq < 4; ++nq) {
        uint32_t r[4], s[4];
        if (!TB) {
            const hf* p = Bh + (wn + nq*16 + (lane & 15))*NT_STRIDE + ks + ((lane >> 4) << 3);
            ldsm4(r, p);
            ldsm4(s, p + BHE);
            bh[2*nq][0]=r[0]; bh[2*nq][1]=r[2]; bh[2*nq+1][0]=r[1]; bh[2*nq+1][1]=r[3];
            bl[2*nq][0]=s[0]; bl[2*nq][1]=s[2]; bl[2*nq+1][0]=s[1]; bl[2*nq+1][1]=s[3];
        } else {
            const hf* p = Bh + (ks + (lane & 15))*T_STRIDE + wn + nq*16 + ((lane >> 4) << 3);
            ldsm4t(r, p);
            ldsm4t(s, p + BHE);
            bh[2*nq][0]=r[0]; bh[2*nq][1]=r[1]; bh[2*nq+1][0]=r[2]; bh[2*nq+1][1]=r[3];
            bl[2*nq][0]=s[0]; bl[2*nq][1]=s[1]; bl[2*nq+1][0]=s[2]; bl[2*nq+1][1]=s[3];
        }
    }
    #pragma unroll
    for (int mt = 0; mt < 2; ++mt)
        #pragma unroll
        for (int nt = 0; nt < 8; ++nt) {
            mma_f16(acc[mt][nt], ah[mt], bh[nt]);
            mma_f16(acc[mt][nt], ah[mt], bl[nt]);
        }
}

template<int TA, int TB>
__device__ __forceinline__ void gemm_core(OpA A, OpB B, int K, float acc[2][8][4],
                                          char* smbase, int tid) {
    const int lane = tid & 31, wid = tid >> 5;
    const int wm = (wid & 3) * 32, wn = (wid >> 2) * 64;
    const int KT = K >> 5;
    stage<TA,TB>(A, B, 0, smbase, tid);
    cp_commit();
    for (int kt = 0; kt < KT; ++kt) {
        if (kt + 1 < KT) stage<TA,TB>(A, B, (kt+1) << 5, smbase + ((kt+1) & 1)*STAGE_B, tid);
        cp_commit();
        cp_wait1();
        __syncthreads();
        char* cur = smbase + (kt & 1)*STAGE_B;
        compute16<TA,TB>(cur, 0,  acc, lane, wm, wn);
        compute16<TA,TB>(cur, 16, acc, lane, wm, wn);
        __syncthreads();
    }
}

#define GEMM_SMEM extern __shared__ char sm_[];

#define EPI_COORDS \
    const int lane = tid & 31, wid = tid >> 5; \
    const int gid = lane >> 2, tig = lane & 3; \
    const int wm = (wid & 3) * 32, wn = (wid >> 2) * 64;

#define EPI_LOOP(BODY) \
    _Pragma("unroll") for (int mt = 0; mt < 2; ++mt) \
    _Pragma("unroll") for (int nt = 0; nt < 8; ++nt) \
    _Pragma("unroll") for (int ci = 0; ci < 4; ++ci) { \
        int mr = wm + mt*16 + gid + ((ci >> 1) ? 8 : 0); \
        int nr = wn + nt*8 + tig*2 + (ci & 1); \
        float v = acc[mt][nt][ci]; \
        BODY \
    }

// ---------------- GEMM kernels ----------------
__global__ void __launch_bounds__(256, 1) tc_proj3() {
    GEMM_SMEM;
    int tid = threadIdx.x;
    int m0 = blockIdx.y * 128, n0 = blockIdx.x * 128;
    int which = blockIdx.z;
    const hf* wh = (which==0) ? d_wqh : (which==1) ? d_wkh : d_wvh;
    const hf* wl = (which==0) ? d_wql : (which==1) ? d_wkl : d_wvl;
    float acc[2][8][4] = {};
    OpA A{d_hsh + (size_t)m0*DD, DD};
    OpB B{wh + (size_t)n0*DD, wl + (size_t)n0*DD, DD};
    gemm_core<0,0>(A, B, DD, acc, sm_, tid);
    EPI_COORDS;
    if (which == 0) {
        EPI_LOOP({
            size_t o = (size_t)(m0+mr)*DD + n0 + nr;
            v = (v > 0.f) ? v + 1.f : expf(v);
            d_sq[o] = v; d_sqh[o] = __float2half_rn(v);
        })
    } else if (which == 1) {
        EPI_LOOP({
            size_t o = (size_t)(m0+mr)*DD + n0 + nr;
            v = (v > 0.f) ? v + 1.f : expf(v);
            d_sk[o] = v; wsplit(d_skh, d_skl, o, v);
        })
    } else {
        EPI_LOOP({
            size_t o = (size_t)(m0+mr)*DD + n0 + nr;
            wsplit(d_vh, d_vl, o, v);
        })
    }
}

__global__ void __launch_bounds__(256, 1) tc_memout() {
    GEMM_SMEM;
    int tid = threadIdx.x;
    int m0 = blockIdx.y * 128, n0 = blockIdx.x * 128;
    float acc[2][8][4] = {};
    OpA A{d_sqh + (size_t)m0*DD, DD};
    OpB B{d_memTh + (size_t)n0*DD, d_memTl + (size_t)n0*DD, DD};
    gemm_core<0,0>(A, B, DD, acc, sm_, tid);
    float act = d_scal[1];
    EPI_COORDS;
    EPI_LOOP({
        d_memout[(size_t)(m0+mr)*DD + n0 + nr] = v * act / d_normq[m0+mr];
    })
}

// G[bn][d][e] = sum_c sk[c][d] * v[c][e]
__global__ void __launch_bounds__(256, 1) tc_kv() {
    GEMM_SMEM;
    int tid = threadIdx.x;
    int bn = blockIdx.z; int b = bn >> 4, n = bn & 15;
    size_t cb = (size_t)(b*SEQ + n*CH)*DD;
    int m0 = blockIdx.y * 128, n0 = blockIdx.x * 128;
    float acc[2][8][4] = {};
    OpA A{d_skh + cb + m0, DD};                    // trans: gmem[c][d], m = d
    OpB B{d_vh + cb + n0, d_vl + cb + n0, DD};     // trans: gmem[c][e], n = e
    gemm_core<1,1>(A, B, CH, acc, sm_, tid);
    float* C = d_G + (size_t)bn*DD*DD;
    EPI_COORDS;
    EPI_LOOP({
        C[(size_t)(m0+mr)*DD + n0 + nr] = v;
    })
}

__global__ void __launch_bounds__(256, 1) tc_scores() {
    GEMM_SMEM;
    int tid = threadIdx.x;
    int bn = blockIdx.z; int b = bn >> 4, n = bn & 15;
    size_t cb = (size_t)(b*SEQ + n*CH)*DD;
    float acc[2][8][4] = {};
    OpA A{d_sqh + cb, DD};
    OpB B{d_skh + cb, d_skl + cb, DD};
    gemm_core<0,0>(A, B, DD, acc, sm_, tid);
    size_t co = (size_t)bn*CH*CH;
    EPI_COORDS;
    EPI_LOOP({
        float m = (nr <= mr) ? v : 0.f;
        size_t o = co + (size_t)mr*CH + nr;
        d_Abuf[o] = m;
        d_Abh[o] = __float2half_rn(m);
    })
}

__global__ void __launch_bounds__(256, 1) tc_attn() {
    GEMM_SMEM;
    int tid = threadIdx.x;
    int bn = blockIdx.z; int b = bn >> 4, n = bn & 15;
    size_t cb = (size_t)(b*SEQ + n*CH)*DD;
    int n0 = blockIdx.x * 128;
    float acc[2][8][4] = {};
    {
        OpA A{d_sqh + cb, DD};
        OpB B{d_Sph + (size_t)bn*DD*DD + n0, d_Spl + (size_t)bn*DD*DD + n0, DD};  // trans [d][e]
        gemm_core<0,1>(A, B, DD, acc, sm_, tid);
    }
    {
        OpA A{d_Abh + (size_t)bn*CH*CH, CH};
        OpB B{d_vh + cb + n0, d_vl + cb + n0, DD};   // trans [c][e]
        gemm_core<0,1>(A, B, CH, acc, sm_, tid);
    }
    EPI_COORDS;
    EPI_LOOP({
        d_local[cb + (size_t)mr*DD + n0 + nr] = v / d_den[bn*CH + mr];
    })
}

__global__ void __launch_bounds__(256, 1) tc_final(float* __restrict__ Out) {
    GEMM_SMEM;
    int tid = threadIdx.x;
    int m0 = blockIdx.y * 128, n0 = blockIdx.x * 128;
    float acc[2][8][4] = {};
    OpA A{d_cmh + (size_t)m0*DD, DD};
    OpB B{d_woh + (size_t)n0*DD, d_wol + (size_t)n0*DD, DD};
    gemm_core<0,0>(A, B, DD, acc, sm_, tid);
    EPI_COORDS;
    EPI_LOOP({
        Out[(size_t)(m0+mr)*DD + n0 + nr] = v;
    })
}

// ---------------- launcher ----------------
extern "C" void kernel_launch(void* const* d_in, const int* in_sizes, int n_in,
                              void* d_out, int out_size) {
    const float* hs    = (const float*)d_in[0];
    const float* wq    = (const float*)d_in[1];
    const float* wk    = (const float*)d_in[2];
    const float* wv    = (const float*)d_in[3];
    const float* wo    = (const float*)d_in[4];
    const float* gate  = (const float*)d_in[5];
    const float* mem   = (const float*)d_in[6];
    const float* mnorm = (const float*)d_in[7];
    float* out = (float*)d_out;

    cudaFuncSetAttribute(tc_proj3,  cudaFuncAttributeMaxDynamicSharedMemorySize, SMEM_TOT);
    cudaFuncSetAttribute(tc_memout, cudaFuncAttributeMaxDynamicSharedMemorySize, SMEM_TOT);
    cudaFuncSetAttribute(tc_kv,     cudaFuncAttributeMaxDynamicSharedMemorySize, SMEM_TOT);
    cudaFuncSetAttribute(tc_scores, cudaFuncAttributeMaxDynamicSharedMemorySize, SMEM_TOT);
    cudaFuncSetAttribute(tc_attn,   cudaFuncAttributeMaxDynamicSharedMemorySize, SMEM_TOT);
    cudaFuncSetAttribute(tc_final,  cudaFuncAttributeMaxDynamicSharedMemorySize, SMEM_TOT);

    scalars_kernel<<<1, 1024>>>(gate, mnorm);

    hf *hsh, *wqh, *wql, *wkh, *wkl, *wvh, *wvl, *woh, *wol;
    cudaGetSymbolAddress((void**)&hsh, d_hsh);
    cudaGetSymbolAddress((void**)&wqh, d_wqh); cudaGetSymbolAddress((void**)&wql, d_wql);
    cudaGetSymbolAddress((void**)&wkh, d_wkh); cudaGetSymbolAddress((void**)&wkl, d_wkl);
    cudaGetSymbolAddress((void**)&wvh, d_wvh); cudaGetSymbolAddress((void**)&wvl, d_wvl);
    cudaGetSymbolAddress((void**)&woh, d_woh); cudaGetSymbolAddress((void**)&wol, d_wol);

    int n4hs = MTOT*DD/4, n4w = DD*DD/4;
    cvt_hi_k<<<(n4hs+255)/256, 256>>>((const float4*)hs, (uint2*)hsh, n4hs);
    cvt_split_k<<<(n4w+255)/256, 256>>>((const float4*)wq, (uint2*)wqh, (uint2*)wql, n4w);
    cvt_split_k<<<(n4w+255)/256, 256>>>((const float4*)wk, (uint2*)wkh, (uint2*)wkl, n4w);
    cvt_split_k<<<(n4w+255)/256, 256>>>((const float4*)wv, (uint2*)wvh, (uint2*)wvl, n4w);
    cvt_split_k<<<(n4w+255)/256, 256>>>((const float4*)wo, (uint2*)woh, (uint2*)wol, n4w);
    cvt_T_k<<<(DD*DD+255)/256, 256>>>(mem);

    dim3 gP(DD/128, MTOT/128, 3);       // (8, 32, 3)
    tc_proj3<<<gP, 256, SMEM_TOT>>>();

    normq_kernel<<<(MTOT*32 + 255)/256, 256>>>(mnorm);
    dim3 gM(DD/128, MTOT/128);          // (8, 32)
    tc_memout<<<gM, 256, SMEM_TOT>>>();

    zc_kernel<<<(BSZ*NCH*DD + 255)/256, 256>>>();
    zprefix_kernel<<<(BSZ*DD + 255)/256, 256>>>();

    dim3 gKV(DD/128, DD/128, BSZ*NCH);  // (8, 8, 32)
    tc_kv<<<gKV, 256, SMEM_TOT>>>();
    gprefix_kernel<<<(int)(((size_t)BSZ*DD*DD + 255)/256), 256>>>();

    dim3 gSc(1, 1, BSZ*NCH);            // (1, 1, 32)
    tc_scores<<<gSc, 256, SMEM_TOT>>>();
    den_kernel<<<(BSZ*NCH*CH*32 + 255)/256, 256>>>();

    dim3 gAt(DD/128, 1, BSZ*NCH);       // (8, 1, 32)
    tc_attn<<<gAt, 256, SMEM_TOT>>>();

    combine_kernel<<<(MTOT*DD + 255)/256, 256>>>();
    tc_final<<<gM, 256, SMEM_TOT>>>(out);
}

// round 8
// speedup vs baseline: 4.8836x; 1.0001x over previous
#include <cuda_runtime.h>
#include <cuda_fp16.h>
#include <math.h>
#include <stdint.h>

#define BSZ 2
#define SEQ 2048
#define DD 1024
#define CH 128
#define NCH 16
#define MTOT (BSZ*SEQ)        // 4096
#define EPSV 1e-6f

typedef __half hf;

// ---------------- scratch ----------------
__device__ float d_sq[MTOT*DD];
__device__ float d_sk[MTOT*DD];
__device__ float d_memout[MTOT*DD];              // stores g*act*memout/normq
__device__ float d_G[(size_t)BSZ*NCH*DD*DD];     // G[bn][d][e] fp32
__device__ float d_zz[BSZ*NCH*DD];
__device__ float d_Abuf[BSZ*NCH*CH*CH];
__device__ float d_den[BSZ*NCH*CH];
__device__ float d_normq[MTOT];
__device__ float d_scal[2];

// fp16 operand buffers. A-side-only matrices hi only; B-side hi+lo.
__device__ hf d_hsh[MTOT*DD];
__device__ hf d_wqh[DD*DD],    d_wql[DD*DD];
__device__ hf d_wkh[DD*DD],    d_wkl[DD*DD];
__device__ hf d_wvh[DD*DD],    d_wvl[DD*DD];
__device__ hf d_woh[DD*DD],    d_wol[DD*DD];
__device__ hf d_memTh[DD*DD],  d_memTl[DD*DD];
__device__ hf d_sqh[MTOT*DD];
__device__ hf d_skh[MTOT*DD],  d_skl[MTOT*DD];
__device__ hf d_vh [MTOT*DD],  d_vl [MTOT*DD];
__device__ hf d_Sph[(size_t)BSZ*NCH*DD*DD], d_Spl[(size_t)BSZ*NCH*DD*DD];
__device__ hf d_Abh[BSZ*NCH*CH*CH];
__device__ hf d_cmh[MTOT*DD];

// ---------------- helpers ----------------
__device__ __forceinline__ void split1(float x, hf& h, hf& l) {
    h = __float2half_rn(x);
    l = __float2half_rn(x - __half2float(h));
}
__device__ __forceinline__ void wsplit(hf* H, hf* L, size_t i, float v) {
    hf h, l; split1(v, h, l); H[i] = h; L[i] = l;
}

// ---------------- small kernels ----------------
__global__ void scalars_kernel(const float* __restrict__ gate,
                               const float* __restrict__ mnorm) {
    __shared__ float sh[1024];
    int t = threadIdx.x;
    sh[t] = mnorm[t];
    __syncthreads();
    for (int s = 512; s > 0; s >>= 1) { if (t < s) sh[t] += sh[t+s]; __syncthreads(); }
    if (t == 0) {
        d_scal[0] = 1.f / (1.f + expf(-gate[0]));
        d_scal[1] = (sh[0] >= EPSV) ? 1.f : 0.f;
    }
}

__device__ __forceinline__ void do_split4(const float4* src, uint2* hi, uint2* lo, int i) {
    float4 x = src[i];
    hf h0,h1,h2,h3,l0,l1,l2,l3;
    split1(x.x,h0,l0); split1(x.y,h1,l1); split1(x.z,h2,l2); split1(x.w,h3,l3);
    union { __half2 b[2]; uint2 u; } uh, ul;
    uh.b[0] = __halves2half2(h0,h1); uh.b[1] = __halves2half2(h2,h3);
    ul.b[0] = __halves2half2(l0,l1); ul.b[1] = __halves2half2(l2,l3);
    hi[i] = uh.u; lo[i] = ul.u;
}

// fused converts: hs (hi only, 4096 blocks) + wq/wk/wv/wo hi+lo (1024 blocks each)
__global__ void cvt_all(const float4* __restrict__ hs,
                        const float4* __restrict__ wq, const float4* __restrict__ wk,
                        const float4* __restrict__ wv, const float4* __restrict__ wo) {
    int bid = blockIdx.x, tid = threadIdx.x;
    if (bid < 4096) {
        int i = bid*256 + tid;
        float4 x = hs[i];
        union { __half2 b[2]; uint2 u; } uh;
        uh.b[0] = __halves2half2(__float2half_rn(x.x), __float2half_rn(x.y));
        uh.b[1] = __halves2half2(__float2half_rn(x.z), __float2half_rn(x.w));
        ((uint2*)d_hsh)[i] = uh.u;
    } else if (bid < 5120) {
        do_split4(wq, (uint2*)d_wqh, (uint2*)d_wql, (bid-4096)*256 + tid);
    } else if (bid < 6144) {
        do_split4(wk, (uint2*)d_wkh, (uint2*)d_wkl, (bid-5120)*256 + tid);
    } else if (bid < 7168) {
        do_split4(wv, (uint2*)d_wvh, (uint2*)d_wvl, (bid-6144)*256 + tid);
    } else {
        do_split4(wo, (uint2*)d_woh, (uint2*)d_wol, (bid-7168)*256 + tid);
    }
}

__global__ void cvt_T_k(const float* __restrict__ src) {
    int idx = blockIdx.x * blockDim.x + threadIdx.x;
    if (idx >= DD*DD) return;
    int k = idx & (DD-1), n = idx >> 10;
    wsplit(d_memTh, d_memTl, (size_t)n*DD + k, src[(size_t)k*DD + n]);
}

__global__ void normq_kernel(const float* __restrict__ mnorm) {
    int warp = (blockIdx.x * blockDim.x + threadIdx.x) >> 5;
    int lane = threadIdx.x & 31;
    if (warp >= MTOT) return;
    const float* row = d_sq + (size_t)warp * DD;
    float s = 0.f;
    for (int k = lane; k < DD; k += 32) s += row[k] * mnorm[k];
    #pragma unroll
    for (int o = 16; o > 0; o >>= 1) s += __shfl_xor_sync(0xffffffffu, s, o);
    if (lane == 0) d_normq[warp] = fmaxf(s, EPSV);
}

__global__ void zc_kernel() {
    int idx = blockIdx.x * blockDim.x + threadIdx.x;
    if (idx >= BSZ*NCH*DD) return;
    int d = idx % DD; int bn = idx / DD;
    int b = bn >> 4, n = bn & 15;
    const float* base = d_sk + (size_t)(b*SEQ + n*CH)*DD + d;
    float s = 0.f;
    #pragma unroll 4
    for (int i = 0; i < CH; ++i) s += base[(size_t)i*DD];
    d_zz[idx] = s;
}

__global__ void zprefix_kernel() {
    int idx = blockIdx.x * blockDim.x + threadIdx.x;
    if (idx >= BSZ*DD) return;
    int b = idx / DD, d = idx % DD;
    float run = 0.f;
    for (int n = 0; n < NCH; ++n) {
        float* p = d_zz + (size_t)(b*NCH + n)*DD + d;
        float t = *p; *p = run; run += t;
    }
}

// ---------------- tensor-core GEMM core (fp16 x2 split) ----------------
#define NT_STRIDE 40
#define T_STRIDE 136
#define MAT_B 10240
#define STAGE_B (3*MAT_B)
#define SMEM_TOT (2*STAGE_B)

__device__ __forceinline__ void cpa16(void* dst, const void* src) {
    uint32_t d = (uint32_t)__cvta_generic_to_shared(dst);
    asm volatile("cp.async.cg.shared.global [%0], [%1], 16;" :: "r"(d), "l"(src));
}
__device__ __forceinline__ void cp_commit() { asm volatile("cp.async.commit_group;"); }
__device__ __forceinline__ void cp_wait1()  { asm volatile("cp.async.wait_group 1;"); }

__device__ __forceinline__ void ldsm4(uint32_t* r, const hf* p) {
    uint32_t a = (uint32_t)__cvta_generic_to_shared(p);
    asm volatile("ldmatrix.sync.aligned.m8n8.x4.shared.b16 {%0,%1,%2,%3}, [%4];"
        : "=r"(r[0]), "=r"(r[1]), "=r"(r[2]), "=r"(r[3]) : "r"(a));
}
__device__ __forceinline__ void ldsm4t(uint32_t* r, const hf* p) {
    uint32_t a = (uint32_t)__cvta_generic_to_shared(p);
    asm volatile("ldmatrix.sync.aligned.m8n8.x4.trans.shared.b16 {%0,%1,%2,%3}, [%4];"
        : "=r"(r[0]), "=r"(r[1]), "=r"(r[2]), "=r"(r[3]) : "r"(a));
}
__device__ __forceinline__ void mma_f16(float* c, const uint32_t* a, const uint32_t* b) {
    asm volatile("mma.sync.aligned.m16n8k16.row.col.f32.f16.f16.f32 "
        "{%0,%1,%2,%3}, {%4,%5,%6,%7}, {%8,%9}, {%0,%1,%2,%3};"
        : "+f"(c[0]), "+f"(c[1]), "+f"(c[2]), "+f"(c[3])
        : "r"(a[0]), "r"(a[1]), "r"(a[2]), "r"(a[3]), "r"(b[0]), "r"(b[1]));
}

struct OpA { const hf* h; int ld; };
struct OpB { const hf *h, *l; int ld; };

template<int TA, int TB>
__device__ __forceinline__ void stage(OpA A, OpB B, int k0, char* sm, int tid) {
    hf* Ah = (hf*)sm;
    hf* Bh = (hf*)(sm + MAT_B);
    hf* Bl = (hf*)(sm + 2*MAT_B);
    #pragma unroll
    for (int i = 0; i < 2; ++i) {
        int idx = tid + 256*i;
        if (!TA) {
            int row = idx >> 2, ch = idx & 3;
            cpa16(Ah + row*NT_STRIDE + ch*8, A.h + (size_t)row*A.ld + k0 + ch*8);
        } else {
            int row = idx >> 4, ch = idx & 15;
            cpa16(Ah + row*T_STRIDE + ch*8, A.h + (size_t)(k0 + row)*A.ld + ch*8);
        }
        if (!TB) {
            int row = idx >> 2, ch = idx & 3;
            size_t so = (size_t)row * B.ld + k0 + ch*8;
            cpa16(Bh + row*NT_STRIDE + ch*8, B.h + so);
            cpa16(Bl + row*NT_STRIDE + ch*8, B.l + so);
        } else {
            int row = idx >> 4, ch = idx & 15;
            size_t so = (size_t)(k0 + row) * B.ld + ch*8;
            cpa16(Bh + row*T_STRIDE + ch*8, B.h + so);
            cpa16(Bl + row*T_STRIDE + ch*8, B.l + so);
        }
    }
}

template<int TA, int TB>
__device__ __forceinline__ void compute16(char* sm, int ks, float acc[2][8][4],
                                          int lane, int wm, int wn) {
    hf* Ah = (hf*)sm;
    hf* Bh = (hf*)(sm + MAT_B);
    const int BHE = MAT_B/2;
    uint32_t ah[2][4], bh[8][2], bl[8][2];
    #pragma unroll
    for (int mt = 0; mt < 2; ++mt) {
        if (!TA) {
            const hf* p = Ah + (wm + mt*16 + (lane & 15))*NT_STRIDE + ks + ((lane >> 4) << 3);
            ldsm4(ah[mt], p);
        } else {
            const hf* p = Ah + (ks + ((lane >> 4) << 3) + (lane & 7))*T_STRIDE + wm + mt*16 + (lane & 8);
            ldsm4t(ah[mt], p);
        }
    }
    #pragma unroll
    for (int nq = 0; nq < 4; ++nq) {
        uint32_t r[4], s[4];
        if (!TB) {
            const hf* p = Bh + (wn + nq*16 + (lane & 15))*NT_STRIDE + ks + ((lane >> 4) << 3);
            ldsm4(r, p);
            ldsm4(s, p + BHE);
            bh[2*nq][0]=r[0]; bh[2*nq][1]=r[2]; bh[2*nq+1][0]=r[1]; bh[2*nq+1][1]=r[3];
            bl[2*nq][0]=s[0]; bl[2*nq][1]=s[2]; bl[2*nq+1][0]=s[1]; bl[2*nq+1][1]=s[3];
        } else {
            const hf* p = Bh + (ks + (lane & 15))*T_STRIDE + wn + nq*16 + ((lane >> 4) << 3);
            ldsm4t(r, p);
            ldsm4t(s, p + BHE);
            bh[2*nq][0]=r[0]; bh[2*nq][1]=r[1]; bh[2*nq+1][0]=r[2]; bh[2*nq+1][1]=r[3];
            bl[2*nq][0]=s[0]; bl[2*nq][1]=s[1]; bl[2*nq+1][0]=s[2]; bl[2*nq+1][1]=s[3];
        }
    }
    #pragma unroll
    for (int mt = 0; mt < 2; ++mt)
        #pragma unroll
        for (int nt = 0; nt < 8; ++nt) {
            mma_f16(acc[mt][nt], ah[mt], bh[nt]);
            mma_f16(acc[mt][nt], ah[mt], bl[nt]);
        }
}

template<int TA, int TB>
__device__ __forceinline__ void gemm_core(OpA A, OpB B, int K, float acc[2][8][4],
                                          char* smbase, int tid) {
    const int lane = tid & 31, wid = tid >> 5;
    const int wm = (wid & 3) * 32, wn = (wid >> 2) * 64;
    const int KT = K >> 5;
    stage<TA,TB>(A, B, 0, smbase, tid);
    cp_commit();
    for (int kt = 0; kt < KT; ++kt) {
        if (kt + 1 < KT) stage<TA,TB>(A, B, (kt+1) << 5, smbase + ((kt+1) & 1)*STAGE_B, tid);
        cp_commit();
        cp_wait1();
        __syncthreads();
        char* cur = smbase + (kt & 1)*STAGE_B;
        compute16<TA,TB>(cur, 0,  acc, lane, wm, wn);
        compute16<TA,TB>(cur, 16, acc, lane, wm, wn);
        __syncthreads();
    }
}

#define GEMM_SMEM extern __shared__ char sm_[];

#define EPI_COORDS \
    const int lane = tid & 31, wid = tid >> 5; \
    const int gid = lane >> 2, tig = lane & 3; \
    const int wm = (wid & 3) * 32, wn = (wid >> 2) * 64;

#define EPI_LOOP(BODY) \
    _Pragma("unroll") for (int mt = 0; mt < 2; ++mt) \
    _Pragma("unroll") for (int nt = 0; nt < 8; ++nt) \
    _Pragma("unroll") for (int ci = 0; ci < 4; ++ci) { \
        int mr = wm + mt*16 + gid + ((ci >> 1) ? 8 : 0); \
        int nr = wn + nt*8 + tig*2 + (ci & 1); \
        float v = acc[mt][nt][ci]; \
        BODY \
    }

// ---------------- GEMM kernels ----------------
__global__ void __launch_bounds__(256, 1) tc_proj3() {
    GEMM_SMEM;
    int tid = threadIdx.x;
    int m0 = blockIdx.y * 128, n0 = blockIdx.x * 128;
    int which = blockIdx.z;
    const hf* wh = (which==0) ? d_wqh : (which==1) ? d_wkh : d_wvh;
    const hf* wl = (which==0) ? d_wql : (which==1) ? d_wkl : d_wvl;
    float acc[2][8][4] = {};
    OpA A{d_hsh + (size_t)m0*DD, DD};
    OpB B{wh + (size_t)n0*DD, wl + (size_t)n0*DD, DD};
    gemm_core<0,0>(A, B, DD, acc, sm_, tid);
    EPI_COORDS;
    if (which == 0) {
        EPI_LOOP({
            size_t o = (size_t)(m0+mr)*DD + n0 + nr;
            v = (v > 0.f) ? v + 1.f : expf(v);
            d_sq[o] = v; d_sqh[o] = __float2half_rn(v);
        })
    } else if (which == 1) {
        EPI_LOOP({
            size_t o = (size_t)(m0+mr)*DD + n0 + nr;
            v = (v > 0.f) ? v + 1.f : expf(v);
            d_sk[o] = v; wsplit(d_skh, d_skl, o, v);
        })
    } else {
        EPI_LOOP({
            size_t o = (size_t)(m0+mr)*DD + n0 + nr;
            wsplit(d_vh, d_vl, o, v);
        })
    }
}

// fused wave2: memout (256 blocks) + kv (2048) + scores (32)
__global__ void __launch_bounds__(256, 1) wave2() {
    GEMM_SMEM;
    int tid = threadIdx.x;
    int bid = blockIdx.x;
    if (bid < 256) {
        // memout: stores g*act*v/normq
        int m0 = (bid >> 3) * 128, n0 = (bid & 7) * 128;
        float acc[2][8][4] = {};
        OpA A{d_sqh + (size_t)m0*DD, DD};
        OpB B{d_memTh + (size_t)n0*DD, d_memTl + (size_t)n0*DD, DD};
        gemm_core<0,0>(A, B, DD, acc, sm_, tid);
        float gs = d_scal[0] * d_scal[1];
        EPI_COORDS;
        EPI_LOOP({
            d_memout[(size_t)(m0+mr)*DD + n0 + nr] = v * gs / d_normq[m0+mr];
        })
    } else if (bid < 2304) {
        // kv: G[bn][d][e] = sum_c sk[c][d] * v[c][e]
        int idx = bid - 256;
        int bn = idx >> 6, loc = idx & 63;
        int b = bn >> 4, n = bn & 15;
        size_t cb = (size_t)(b*SEQ + n*CH)*DD;
        int m0 = (loc >> 3) * 128, n0 = (loc & 7) * 128;
        float acc[2][8][4] = {};
        OpA A{d_skh + cb + m0, DD};
        OpB B{d_vh + cb + n0, d_vl + cb + n0, DD};
        gemm_core<1,1>(A, B, CH, acc, sm_, tid);
        float* C = d_G + (size_t)bn*DD*DD;
        EPI_COORDS;
        EPI_LOOP({
            C[(size_t)(m0+mr)*DD + n0 + nr] = v;
        })
    } else {
        // scores
        int bn = bid - 2304;
        int b = bn >> 4, n = bn & 15;
        size_t cb = (size_t)(b*SEQ + n*CH)*DD;
        float acc[2][8][4] = {};
        OpA A{d_sqh + cb, DD};
        OpB B{d_skh + cb, d_skl + cb, DD};
        gemm_core<0,0>(A, B, DD, acc, sm_, tid);
        size_t co = (size_t)bn*CH*CH;
        EPI_COORDS;
        EPI_LOOP({
            float m = (nr <= mr) ? v : 0.f;
            size_t o = co + (size_t)mr*CH + nr;
            d_Abuf[o] = m;
            d_Abh[o] = __float2half_rn(m);
        })
    }
}

// fused wave3: gprefix (8192 blocks) + den (512 blocks)
__global__ void __launch_bounds__(256) wave3() {
    int bid = blockIdx.x, tid = threadIdx.x;
    if (bid < 8192) {
        size_t idx = (size_t)bid*256 + tid;
        int b = (int)(idx / ((size_t)DD*DD));
        size_t rem = idx % ((size_t)DD*DD);
        float run = 0.f;
        for (int n = 0; n < NCH; ++n) {
            size_t off = ((size_t)(b*NCH + n)*DD*DD) + rem;
            float t = d_G[off];
            wsplit(d_Sph, d_Spl, off, run);
            run += t;
        }
    } else {
        int warp = ((bid - 8192)*256 + tid) >> 5;
        int lane = tid & 31;
        if (warp >= BSZ*NCH*CH) return;
        int bn = warp / CH, i = warp % CH;
        int b = bn >> 4, n = bn & 15;
        const float* qr = d_sq + (size_t)(b*SEQ + n*CH + i)*DD;
        const float* zr = d_zz + (size_t)bn*DD;
        float s = 0.f;
        for (int k = lane; k < DD; k += 32) s += qr[k] * zr[k];
        const float* ar = d_Abuf + (size_t)bn*CH*CH + (size_t)i*CH;
        for (int j = lane; j < CH; j += 32) s += ar[j];
        #pragma unroll
        for (int o = 16; o > 0; o >>= 1) s += __shfl_xor_sync(0xffffffffu, s, o);
        if (lane == 0) d_den[warp] = fmaxf(s, EPSV);
    }
}

// attn: local = (sq @ Sp + Abuf @ v)/den; epilogue fuses combine -> d_cmh
__global__ void __launch_bounds__(256, 1) tc_attn() {
    GEMM_SMEM;
    int tid = threadIdx.x;
    int bn = blockIdx.z; int b = bn >> 4, n = bn & 15;
    size_t cb = (size_t)(b*SEQ + n*CH)*DD;
    int n0 = blockIdx.x * 128;
    float acc[2][8][4] = {};
    {
        OpA A{d_sqh + cb, DD};
        OpB B{d_Sph + (size_t)bn*DD*DD + n0, d_Spl + (size_t)bn*DD*DD + n0, DD};
        gemm_core<0,1>(A, B, DD, acc, sm_, tid);
    }
    {
        OpA A{d_Abh + (size_t)bn*CH*CH, CH};
        OpB B{d_vh + cb + n0, d_vl + cb + n0, DD};
        gemm_core<0,1>(A, B, CH, acc, sm_, tid);
    }
    float og = 1.f - d_scal[0];
    EPI_COORDS;
    EPI_LOOP({
        size_t o = cb + (size_t)mr*DD + n0 + nr;
        float cm = d_memout[o] + og * v / d_den[bn*CH + mr];
        d_cmh[o] = __float2half_rn(cm);
    })
}

__global__ void __launch_bounds__(256, 1) tc_final(float* __restrict__ Out) {
    GEMM_SMEM;
    int tid = threadIdx.x;
    int m0 = blockIdx.y * 128, n0 = blockIdx.x * 128;
    float acc[2][8][4] = {};
    OpA A{d_cmh + (size_t)m0*DD, DD};
    OpB B{d_woh + (size_t)n0*DD, d_wol + (size_t)n0*DD, DD};
    gemm_core<0,0>(A, B, DD, acc, sm_, tid);
    EPI_COORDS;
    EPI_LOOP({
        Out[(size_t)(m0+mr)*DD + n0 + nr] = v;
    })
}

// ---------------- launcher ----------------
extern "C" void kernel_launch(void* const* d_in, const int* in_sizes, int n_in,
                              void* d_out, int out_size) {
    const float* hs    = (const float*)d_in[0];
    const float* wq    = (const float*)d_in[1];
    const float* wk    = (const float*)d_in[2];
    const float* wv    = (const float*)d_in[3];
    const float* wo    = (const float*)d_in[4];
    const float* gate  = (const float*)d_in[5];
    const float* mem   = (const float*)d_in[6];
    const float* mnorm = (const float*)d_in[7];
    float* out = (float*)d_out;

    cudaFuncSetAttribute(tc_proj3, cudaFuncAttributeMaxDynamicSharedMemorySize, SMEM_TOT);
    cudaFuncSetAttribute(wave2,    cudaFuncAttributeMaxDynamicSharedMemorySize, SMEM_TOT);
    cudaFuncSetAttribute(tc_attn,  cudaFuncAttributeMaxDynamicSharedMemorySize, SMEM_TOT);
    cudaFuncSetAttribute(tc_final, cudaFuncAttributeMaxDynamicSharedMemorySize, SMEM_TOT);

    scalars_kernel<<<1, 1024>>>(gate, mnorm);

    cvt_all<<<8192, 256>>>((const float4*)hs, (const float4*)wq, (const float4*)wk,
                           (const float4*)wv, (const float4*)wo);
    cvt_T_k<<<(DD*DD+255)/256, 256>>>(mem);

    dim3 gP(DD/128, MTOT/128, 3);       // (8, 32, 3)
    tc_proj3<<<gP, 256, SMEM_TOT>>>();

    normq_kernel<<<(MTOT*32 + 255)/256, 256>>>(mnorm);
    zc_kernel<<<(BSZ*NCH*DD + 255)/256, 256>>>();
    zprefix_kernel<<<(BSZ*DD + 255)/256, 256>>>();

    wave2<<<2336, 256, SMEM_TOT>>>();
    wave3<<<8704, 256>>>();

    dim3 gAt(DD/128, 1, BSZ*NCH);       // (8, 1, 32)
    tc_attn<<<gAt, 256, SMEM_TOT>>>();

    dim3 gM(DD/128, MTOT/128);          // (8, 32)
    tc_final<<<gM, 256, SMEM_TOT>>>(out);
}

// round 9
// speedup vs baseline: 5.3579x; 1.0971x over previous
#include <cuda_runtime.h>
#include <cuda_fp16.h>
#include <math.h>
#include <stdint.h>

#define BSZ 2
#define SEQ 2048
#define DD 1024
#define CH 128
#define NCH 16
#define MTOT (BSZ*SEQ)        // 4096
#define EPSV 1e-6f

typedef __half hf;

// ---------------- scratch ----------------
__device__ float d_sq[MTOT*DD];
__device__ float d_sk[MTOT*DD];
__device__ float d_memout[MTOT*DD];              // stores g*act*memout/normq
__device__ float d_G[(size_t)BSZ*NCH*DD*DD];     // G[bn][d][e] fp32
__device__ float d_zz[BSZ*NCH*DD];
__device__ float d_Abuf[BSZ*NCH*CH*CH];
__device__ float d_den[BSZ*NCH*CH];
__device__ float d_normq[MTOT];
__device__ float d_scal[2];

__device__ hf d_hsh[MTOT*DD];
__device__ hf d_wqh[DD*DD],    d_wql[DD*DD];
__device__ hf d_wkh[DD*DD],    d_wkl[DD*DD];
__device__ hf d_wvh[DD*DD],    d_wvl[DD*DD];
__device__ hf d_woh[DD*DD],    d_wol[DD*DD];
__device__ hf d_memTh[DD*DD],  d_memTl[DD*DD];
__device__ hf d_sqh[MTOT*DD];
__device__ hf d_skh[MTOT*DD],  d_skl[MTOT*DD];
__device__ hf d_vh [MTOT*DD],  d_vl [MTOT*DD];
__device__ hf d_Sph[(size_t)BSZ*NCH*DD*DD], d_Spl[(size_t)BSZ*NCH*DD*DD];
__device__ hf d_Abh[BSZ*NCH*CH*CH];
__device__ hf d_cmh[MTOT*DD];

// ---------------- helpers ----------------
__device__ __forceinline__ void split1(float x, hf& h, hf& l) {
    h = __float2half_rn(x);
    l = __float2half_rn(x - __half2float(h));
}
__device__ __forceinline__ void wsplit(hf* H, hf* L, size_t i, float v) {
    hf h, l; split1(v, h, l); H[i] = h; L[i] = l;
}

// ---------------- small kernels ----------------
__global__ void scalars_kernel(const float* __restrict__ gate,
                               const float* __restrict__ mnorm) {
    __shared__ float sh[1024];
    int t = threadIdx.x;
    sh[t] = mnorm[t];
    __syncthreads();
    for (int s = 512; s > 0; s >>= 1) { if (t < s) sh[t] += sh[t+s]; __syncthreads(); }
    if (t == 0) {
        d_scal[0] = 1.f / (1.f + expf(-gate[0]));
        d_scal[1] = (sh[0] >= EPSV) ? 1.f : 0.f;
    }
}

__device__ __forceinline__ void do_split4(const float4* src, uint2* hi, uint2* lo, int i) {
    float4 x = src[i];
    hf h0,h1,h2,h3,l0,l1,l2,l3;
    split1(x.x,h0,l0); split1(x.y,h1,l1); split1(x.z,h2,l2); split1(x.w,h3,l3);
    union { __half2 b[2]; uint2 u; } uh, ul;
    uh.b[0] = __halves2half2(h0,h1); uh.b[1] = __halves2half2(h2,h3);
    ul.b[0] = __halves2half2(l0,l1); ul.b[1] = __halves2half2(l2,l3);
    hi[i] = uh.u; lo[i] = ul.u;
}

__global__ void cvt_all(const float4* __restrict__ hs,
                        const float4* __restrict__ wq, const float4* __restrict__ wk,
                        const float4* __restrict__ wv, const float4* __restrict__ wo) {
    int bid = blockIdx.x, tid = threadIdx.x;
    if (bid < 4096) {
        int i = bid*256 + tid;
        float4 x = hs[i];
        union { __half2 b[2]; uint2 u; } uh;
        uh.b[0] = __halves2half2(__float2half_rn(x.x), __float2half_rn(x.y));
        uh.b[1] = __halves2half2(__float2half_rn(x.z), __float2half_rn(x.w));
        ((uint2*)d_hsh)[i] = uh.u;
    } else if (bid < 5120) {
        do_split4(wq, (uint2*)d_wqh, (uint2*)d_wql, (bid-4096)*256 + tid);
    } else if (bid < 6144) {
        do_split4(wk, (uint2*)d_wkh, (uint2*)d_wkl, (bid-5120)*256 + tid);
    } else if (bid < 7168) {
        do_split4(wv, (uint2*)d_wvh, (uint2*)d_wvl, (bid-6144)*256 + tid);
    } else {
        do_split4(wo, (uint2*)d_woh, (uint2*)d_wol, (bid-7168)*256 + tid);
    }
}

__global__ void cvt_T_k(const float* __restrict__ src) {
    int idx = blockIdx.x * blockDim.x + threadIdx.x;
    if (idx >= DD*DD) return;
    int k = idx & (DD-1), n = idx >> 10;
    wsplit(d_memTh, d_memTl, (size_t)n*DD + k, src[(size_t)k*DD + n]);
}

__global__ void normq_kernel(const float* __restrict__ mnorm) {
    int warp = (blockIdx.x * blockDim.x + threadIdx.x) >> 5;
    int lane = threadIdx.x & 31;
    if (warp >= MTOT) return;
    const float* row = d_sq + (size_t)warp * DD;
    float s = 0.f;
    for (int k = lane; k < DD; k += 32) s += row[k] * mnorm[k];
    #pragma unroll
    for (int o = 16; o > 0; o >>= 1) s += __shfl_xor_sync(0xffffffffu, s, o);
    if (lane == 0) d_normq[warp] = fmaxf(s, EPSV);
}

__global__ void zc_kernel() {
    int idx = blockIdx.x * blockDim.x + threadIdx.x;
    if (idx >= BSZ*NCH*DD) return;
    int d = idx % DD; int bn = idx / DD;
    int b = bn >> 4, n = bn & 15;
    const float* base = d_sk + (size_t)(b*SEQ + n*CH)*DD + d;
    float s = 0.f;
    #pragma unroll 4
    for (int i = 0; i < CH; ++i) s += base[(size_t)i*DD];
    d_zz[idx] = s;
}

__global__ void zprefix_kernel() {
    int idx = blockIdx.x * blockDim.x + threadIdx.x;
    if (idx >= BSZ*DD) return;
    int b = idx / DD, d = idx % DD;
    float run = 0.f;
    for (int n = 0; n < NCH; ++n) {
        float* p = d_zz + (size_t)(b*NCH + n)*DD + d;
        float t = *p; *p = run; run += t;
    }
}

// ---------------- tensor-core GEMM core (fp16 x2 split) ----------------
#define NT_STRIDE 40
#define T_STRIDE 136
#define MAT_B 10240
#define STAGE_B (3*MAT_B)
#define SMEM_TOT (2*STAGE_B)

__device__ __forceinline__ void cpa16(void* dst, const void* src) {
    uint32_t d = (uint32_t)__cvta_generic_to_shared(dst);
    asm volatile("cp.async.cg.shared.global [%0], [%1], 16;" :: "r"(d), "l"(src));
}
__device__ __forceinline__ void cp_commit() { asm volatile("cp.async.commit_group;"); }
__device__ __forceinline__ void cp_wait1()  { asm volatile("cp.async.wait_group 1;"); }

__device__ __forceinline__ void ldsm4a(uint32_t* r, uint32_t a) {
    asm volatile("ldmatrix.sync.aligned.m8n8.x4.shared.b16 {%0,%1,%2,%3}, [%4];"
        : "=r"(r[0]), "=r"(r[1]), "=r"(r[2]), "=r"(r[3]) : "r"(a));
}
__device__ __forceinline__ void ldsm4ta(uint32_t* r, uint32_t a) {
    asm volatile("ldmatrix.sync.aligned.m8n8.x4.trans.shared.b16 {%0,%1,%2,%3}, [%4];"
        : "=r"(r[0]), "=r"(r[1]), "=r"(r[2]), "=r"(r[3]) : "r"(a));
}
__device__ __forceinline__ void mma_f16(float* c, const uint32_t* a, const uint32_t* b) {
    asm volatile("mma.sync.aligned.m16n8k16.row.col.f32.f16.f16.f32 "
        "{%0,%1,%2,%3}, {%4,%5,%6,%7}, {%8,%9}, {%0,%1,%2,%3};"
        : "+f"(c[0]), "+f"(c[1]), "+f"(c[2]), "+f"(c[3])
        : "r"(a[0]), "r"(a[1]), "r"(a[2]), "r"(a[3]), "r"(b[0]), "r"(b[1]));
}

struct OpA { const hf* h; int ld; };
struct OpB { const hf *h, *l; int ld; };

template<int TA, int TB>
__device__ __forceinline__ void stage(OpA A, OpB B, int k0, char* sm, int tid) {
    hf* Ah = (hf*)sm;
    hf* Bh = (hf*)(sm + MAT_B);
    hf* Bl = (hf*)(sm + 2*MAT_B);
    #pragma unroll
    for (int i = 0; i < 2; ++i) {
        int idx = tid + 256*i;
        if (!TA) {
            int row = idx >> 2, ch = idx & 3;
            cpa16(Ah + row*NT_STRIDE + ch*8, A.h + (size_t)row*A.ld + k0 + ch*8);
        } else {
            int row = idx >> 4, ch = idx & 15;
            cpa16(Ah + row*T_STRIDE + ch*8, A.h + (size_t)(k0 + row)*A.ld + ch*8);
        }
        if (!TB) {
            int row = idx >> 2, ch = idx & 3;
            size_t so = (size_t)row * B.ld + k0 + ch*8;
            cpa16(Bh + row*NT_STRIDE + ch*8, B.h + so);
            cpa16(Bl + row*NT_STRIDE + ch*8, B.l + so);
        } else {
            int row = idx >> 4, ch = idx & 15;
            size_t so = (size_t)(k0 + row) * B.ld + ch*8;
            cpa16(Bh + row*T_STRIDE + ch*8, B.h + so);
            cpa16(Bl + row*T_STRIDE + ch*8, B.l + so);
        }
    }
}

// precomputed per-lane smem byte offsets (relative to stage base) for ldmatrix
struct LaneOff {
    uint32_t a[2];   // A fragment offsets for ks=0 (add 2*ks bytes for ks=16)
    uint32_t b[4];   // B hi fragment offsets (Bl = +MAT_B/... computed inside)
};
template<int TA, int TB>
__device__ __forceinline__ LaneOff make_off(int lane, int wm, int wn) {
    LaneOff lo;
    #pragma unroll
    for (int mt = 0; mt < 2; ++mt) {
        lo.a[mt] = (!TA)
            ? (uint32_t)(((wm + mt*16 + (lane & 15))*NT_STRIDE + ((lane >> 4) << 3)) * 2)
            : (uint32_t)(((((lane >> 4) << 3) + (lane & 7))*T_STRIDE + wm + mt*16 + (lane & 8)) * 2);
    }
    #pragma unroll
    for (int nq = 0; nq < 4; ++nq) {
        lo.b[nq] = (!TB)
            ? (uint32_t)(MAT_B + ((wn + nq*16 + (lane & 15))*NT_STRIDE + ((lane >> 4) << 3)) * 2)
            : (uint32_t)(MAT_B + (((lane & 15))*T_STRIDE + wn + nq*16 + ((lane >> 4) << 3)) * 2);
    }
    return lo;
}

template<int TA, int TB>
__device__ __forceinline__ void compute16(uint32_t smaddr, int ks, const LaneOff& lo,
                                          float acc[2][8][4]) {
    // byte delta for k-step: non-trans A: +2*ks along row; trans A: +ks rows
    const uint32_t dA = (!TA) ? (uint32_t)(2*ks) : (uint32_t)(2*ks*T_STRIDE);
    const uint32_t dB = (!TB) ? (uint32_t)(2*ks) : (uint32_t)(2*ks*T_STRIDE);
    uint32_t ah[2][4], bh[8][2], bl[8][2];
    #pragma unroll
    for (int mt = 0; mt < 2; ++mt) {
        uint32_t a = smaddr + lo.a[mt] + dA;
        if (!TA) ldsm4a(ah[mt], a); else ldsm4ta(ah[mt], a);
    }
    #pragma unroll
    for (int nq = 0; nq < 4; ++nq) {
        uint32_t a = smaddr + lo.b[nq] + dB;
        uint32_t r[4], s[4];
        if (!TB) {
            ldsm4a(r, a);
            ldsm4a(s, a + MAT_B);
            bh[2*nq][0]=r[0]; bh[2*nq][1]=r[2]; bh[2*nq+1][0]=r[1]; bh[2*nq+1][1]=r[3];
            bl[2*nq][0]=s[0]; bl[2*nq][1]=s[2]; bl[2*nq+1][0]=s[1]; bl[2*nq+1][1]=s[3];
        } else {
            ldsm4ta(r, a);
            ldsm4ta(s, a + MAT_B);
            bh[2*nq][0]=r[0]; bh[2*nq][1]=r[1]; bh[2*nq+1][0]=r[2]; bh[2*nq+1][1]=r[3];
            bl[2*nq][0]=s[0]; bl[2*nq][1]=s[1]; bl[2*nq+1][0]=s[2]; bl[2*nq+1][1]=s[3];
        }
    }
    #pragma unroll
    for (int mt = 0; mt < 2; ++mt)
        #pragma unroll
        for (int nt = 0; nt < 8; ++nt) {
            mma_f16(acc[mt][nt], ah[mt], bh[nt]);
            mma_f16(acc[mt][nt], ah[mt], bl[nt]);
        }
}

template<int TA, int TB>
__device__ __forceinline__ void gemm_core(OpA A, OpB B, int K, float acc[2][8][4],
                                          char* smbase, int tid) {
    const int lane = tid & 31, wid = tid >> 5;
    const int wm = (wid & 3) * 32, wn = (wid >> 2) * 64;
    const LaneOff lo = make_off<TA,TB>(lane, wm, wn);
    const uint32_t base0 = (uint32_t)__cvta_generic_to_shared(smbase);
    const int KT = K >> 5;
    stage<TA,TB>(A, B, 0, smbase, tid);
    cp_commit();
    for (int kt = 0; kt < KT; ++kt) {
        if (kt + 1 < KT) stage<TA,TB>(A, B, (kt+1) << 5, smbase + ((kt+1) & 1)*STAGE_B, tid);
        cp_commit();
        cp_wait1();
        __syncthreads();
        uint32_t cur = base0 + (uint32_t)((kt & 1)*STAGE_B);
        compute16<TA,TB>(cur, 0,  lo, acc);
        compute16<TA,TB>(cur, 16, lo, acc);
        __syncthreads();
    }
}

#define GEMM_SMEM extern __shared__ char sm_[];

#define EPI_COORDS \
    const int lane = tid & 31, wid = tid >> 5; \
    const int gid = lane >> 2, tig = lane & 3; \
    const int wm = (wid & 3) * 32, wn = (wid >> 2) * 64;

#define EPI_LOOP(BODY) \
    _Pragma("unroll") for (int mt = 0; mt < 2; ++mt) \
    _Pragma("unroll") for (int nt = 0; nt < 8; ++nt) \
    _Pragma("unroll") for (int ci = 0; ci < 4; ++ci) { \
        int mr = wm + mt*16 + gid + ((ci >> 1) ? 8 : 0); \
        int nr = wn + nt*8 + tig*2 + (ci & 1); \
        float v = acc[mt][nt][ci]; \
        BODY \
    }

// ---------------- GEMM kernels ----------------
__global__ void __launch_bounds__(256, 2) tc_proj3() {
    GEMM_SMEM;
    int tid = threadIdx.x;
    int m0 = blockIdx.y * 128, n0 = blockIdx.x * 128;
    int which = blockIdx.z;
    const hf* wh = (which==0) ? d_wqh : (which==1) ? d_wkh : d_wvh;
    const hf* wl = (which==0) ? d_wql : (which==1) ? d_wkl : d_wvl;
    float acc[2][8][4] = {};
    OpA A{d_hsh + (size_t)m0*DD, DD};
    OpB B{wh + (size_t)n0*DD, wl + (size_t)n0*DD, DD};
    gemm_core<0,0>(A, B, DD, acc, sm_, tid);
    EPI_COORDS;
    if (which == 0) {
        EPI_LOOP({
            size_t o = (size_t)(m0+mr)*DD + n0 + nr;
            v = (v > 0.f) ? v + 1.f : expf(v);
            d_sq[o] = v; d_sqh[o] = __float2half_rn(v);
        })
    } else if (which == 1) {
        EPI_LOOP({
            size_t o = (size_t)(m0+mr)*DD + n0 + nr;
            v = (v > 0.f) ? v + 1.f : expf(v);
            d_sk[o] = v; wsplit(d_skh, d_skl, o, v);
        })
    } else {
        EPI_LOOP({
            size_t o = (size_t)(m0+mr)*DD + n0 + nr;
            wsplit(d_vh, d_vl, o, v);
        })
    }
}

// fused wave2: memout (256 blocks) + kv (2048) + scores (32)
__global__ void __launch_bounds__(256, 2) wave2() {
    GEMM_SMEM;
    int tid = threadIdx.x;
    int bid = blockIdx.x;
    if (bid < 256) {
        int m0 = (bid >> 3) * 128, n0 = (bid & 7) * 128;
        float acc[2][8][4] = {};
        OpA A{d_sqh + (size_t)m0*DD, DD};
        OpB B{d_memTh + (size_t)n0*DD, d_memTl + (size_t)n0*DD, DD};
        gemm_core<0,0>(A, B, DD, acc, sm_, tid);
        float gs = d_scal[0] * d_scal[1];
        EPI_COORDS;
        EPI_LOOP({
            d_memout[(size_t)(m0+mr)*DD + n0 + nr] = v * gs / d_normq[m0+mr];
        })
    } else if (bid < 2304) {
        int idx = bid - 256;
        int bn = idx >> 6, loc = idx & 63;
        int b = bn >> 4, n = bn & 15;
        size_t cb = (size_t)(b*SEQ + n*CH)*DD;
        int m0 = (loc >> 3) * 128, n0 = (loc & 7) * 128;
        float acc[2][8][4] = {};
        OpA A{d_skh + cb + m0, DD};
        OpB B{d_vh + cb + n0, d_vl + cb + n0, DD};
        gemm_core<1,1>(A, B, CH, acc, sm_, tid);
        float* C = d_G + (size_t)bn*DD*DD;
        EPI_COORDS;
        EPI_LOOP({
            C[(size_t)(m0+mr)*DD + n0 + nr] = v;
        })
    } else {
        int bn = bid - 2304;
        int b = bn >> 4, n = bn & 15;
        size_t cb = (size_t)(b*SEQ + n*CH)*DD;
        float acc[2][8][4] = {};
        OpA A{d_sqh + cb, DD};
        OpB B{d_skh + cb, d_skl + cb, DD};
        gemm_core<0,0>(A, B, DD, acc, sm_, tid);
        size_t co = (size_t)bn*CH*CH;
        EPI_COORDS;
        EPI_LOOP({
            float m = (nr <= mr) ? v : 0.f;
            size_t o = co + (size_t)mr*CH + nr;
            d_Abuf[o] = m;
            d_Abh[o] = __float2half_rn(m);
        })
    }
}

// fused wave3: gprefix (8192 blocks) + den (512 blocks)
__global__ void __launch_bounds__(256) wave3() {
    int bid = blockIdx.x, tid = threadIdx.x;
    if (bid < 8192) {
        size_t idx = (size_t)bid*256 + tid;
        int b = (int)(idx / ((size_t)DD*DD));
        size_t rem = idx % ((size_t)DD*DD);
        float run = 0.f;
        for (int n = 0; n < NCH; ++n) {
            size_t off = ((size_t)(b*NCH + n)*DD*DD) + rem;
            float t = d_G[off];
            wsplit(d_Sph, d_Spl, off, run);
            run += t;
        }
    } else {
        int warp = ((bid - 8192)*256 + tid) >> 5;
        int lane = tid & 31;
        if (warp >= BSZ*NCH*CH) return;
        int bn = warp / CH, i = warp % CH;
        int b = bn >> 4, n = bn & 15;
        const float* qr = d_sq + (size_t)(b*SEQ + n*CH + i)*DD;
        const float* zr = d_zz + (size_t)bn*DD;
        float s = 0.f;
        for (int k = lane; k < DD; k += 32) s += qr[k] * zr[k];
        const float* ar = d_Abuf + (size_t)bn*CH*CH + (size_t)i*CH;
        for (int j = lane; j < CH; j += 32) s += ar[j];
        #pragma unroll
        for (int o = 16; o > 0; o >>= 1) s += __shfl_xor_sync(0xffffffffu, s, o);
        if (lane == 0) d_den[warp] = fmaxf(s, EPSV);
    }
}

// attn: local = (sq @ Sp + Abuf @ v)/den; epilogue fuses combine -> d_cmh
__global__ void __launch_bounds__(256, 2) tc_attn() {
    GEMM_SMEM;
    int tid = threadIdx.x;
    int bn = blockIdx.z; int b = bn >> 4, n = bn & 15;
    size_t cb = (size_t)(b*SEQ + n*CH)*DD;
    int n0 = blockIdx.x * 128;
    float acc[2][8][4] = {};
    {
        OpA A{d_sqh + cb, DD};
        OpB B{d_Sph + (size_t)bn*DD*DD + n0, d_Spl + (size_t)bn*DD*DD + n0, DD};
        gemm_core<0,1>(A, B, DD, acc, sm_, tid);
    }
    {
        OpA A{d_Abh + (size_t)bn*CH*CH, CH};
        OpB B{d_vh + cb + n0, d_vl + cb + n0, DD};
        gemm_core<0,1>(A, B, CH, acc, sm_, tid);
    }
    float og = 1.f - d_scal[0];
    EPI_COORDS;
    EPI_LOOP({
        size_t o = cb + (size_t)mr*DD + n0 + nr;
        float cm = d_memout[o] + og * v / d_den[bn*CH + mr];
        d_cmh[o] = __float2half_rn(cm);
    })
}

__global__ void __launch_bounds__(256, 2) tc_final(float* __restrict__ Out) {
    GEMM_SMEM;
    int tid = threadIdx.x;
    int m0 = blockIdx.y * 128, n0 = blockIdx.x * 128;
    float acc[2][8][4] = {};
    OpA A{d_cmh + (size_t)m0*DD, DD};
    OpB B{d_woh + (size_t)n0*DD, d_wol + (size_t)n0*DD, DD};
    gemm_core<0,0>(A, B, DD, acc, sm_, tid);
    EPI_COORDS;
    EPI_LOOP({
        Out[(size_t)(m0+mr)*DD + n0 + nr] = v;
    })
}

// ---------------- launcher ----------------
extern "C" void kernel_launch(void* const* d_in, const int* in_sizes, int n_in,
                              void* d_out, int out_size) {
    const float* hs    = (const float*)d_in[0];
    const float* wq    = (const float*)d_in[1];
    const float* wk    = (const float*)d_in[2];
    const float* wv    = (const float*)d_in[3];
    const float* wo    = (const float*)d_in[4];
    const float* gate  = (const float*)d_in[5];
    const float* mem   = (const float*)d_in[6];
    const float* mnorm = (const float*)d_in[7];
    float* out = (float*)d_out;

    cudaFuncSetAttribute(tc_proj3, cudaFuncAttributeMaxDynamicSharedMemorySize, SMEM_TOT);
    cudaFuncSetAttribute(wave2,    cudaFuncAttributeMaxDynamicSharedMemorySize, SMEM_TOT);
    cudaFuncSetAttribute(tc_attn,  cudaFuncAttributeMaxDynamicSharedMemorySize, SMEM_TOT);
    cudaFuncSetAttribute(tc_final, cudaFuncAttributeMaxDynamicSharedMemorySize, SMEM_TOT);

    scalars_kernel<<<1, 1024>>>(gate, mnorm);

    cvt_all<<<8192, 256>>>((const float4*)hs, (const float4*)wq, (const float4*)wk,
                           (const float4*)wv, (const float4*)wo);
    cvt_T_k<<<(DD*DD+255)/256, 256>>>(mem);

    dim3 gP(DD/128, MTOT/128, 3);       // (8, 32, 3)
    tc_proj3<<<gP, 256, SMEM_TOT>>>();

    normq_kernel<<<(MTOT*32 + 255)/256, 256>>>(mnorm);
    zc_kernel<<<(BSZ*NCH*DD + 255)/256, 256>>>();
    zprefix_kernel<<<(BSZ*DD + 255)/256, 256>>>();

    wave2<<<2336, 256, SMEM_TOT>>>();
    wave3<<<8704, 256>>>();

    dim3 gAt(DD/128, 1, BSZ*NCH);       // (8, 1, 32)
    tc_attn<<<gAt, 256, SMEM_TOT>>>();

    dim3 gM(DD/128, MTOT/128);          // (8, 32)
    tc_final<<<gM, 256, SMEM_TOT>>>(out);
}

// round 10
// speedup vs baseline: 7.8680x; 1.4685x over previous
#include <cuda_runtime.h>
#include <cuda_fp16.h>
#include <math.h>
#include <stdint.h>

#define BSZ 2
#define SEQ 2048
#define DD 1024
#define CH 128
#define NCH 16
#define MTOT (BSZ*SEQ)        // 4096
#define EPSV 1e-6f

typedef __half hf;

// ---------------- scratch ----------------
__device__ float d_sq[MTOT*DD];
__device__ float d_sk[MTOT*DD];
__device__ float d_memout[MTOT*DD];              // stores g*act*memout/normq
__device__ float d_G[(size_t)BSZ*NCH*DD*DD];     // G[bn][d][e] fp32
__device__ float d_zz[BSZ*NCH*DD];
__device__ float d_Abuf[BSZ*NCH*CH*CH];
__device__ float d_den[BSZ*NCH*CH];
__device__ float d_normq[MTOT];
__device__ float d_scal[2];

// fp16 operand buffers (hi only — single-pass fp16 GEMMs)
__device__ hf d_hsh[MTOT*DD];
__device__ hf d_wqh[DD*DD];
__device__ hf d_wkh[DD*DD];
__device__ hf d_wvh[DD*DD];
__device__ hf d_woh[DD*DD];
__device__ hf d_memTh[DD*DD];
__device__ hf d_sqh[MTOT*DD];
__device__ hf d_skh[MTOT*DD];
__device__ hf d_vh [MTOT*DD];
__device__ hf d_Sph[(size_t)BSZ*NCH*DD*DD];
__device__ hf d_Abh[BSZ*NCH*CH*CH];
__device__ hf d_cmh[MTOT*DD];

// ---------------- small kernels ----------------
__global__ void scalars_kernel(const float* __restrict__ gate,
                               const float* __restrict__ mnorm) {
    __shared__ float sh[1024];
    int t = threadIdx.x;
    sh[t] = mnorm[t];
    __syncthreads();
    for (int s = 512; s > 0; s >>= 1) { if (t < s) sh[t] += sh[t+s]; __syncthreads(); }
    if (t == 0) {
        d_scal[0] = 1.f / (1.f + expf(-gate[0]));
        d_scal[1] = (sh[0] >= EPSV) ? 1.f : 0.f;
    }
}

__device__ __forceinline__ void cvt4hi(const float4* src, uint2* hi, int i) {
    float4 x = src[i];
    union { __half2 b[2]; uint2 u; } uh;
    uh.b[0] = __halves2half2(__float2half_rn(x.x), __float2half_rn(x.y));
    uh.b[1] = __halves2half2(__float2half_rn(x.z), __float2half_rn(x.w));
    hi[i] = uh.u;
}

// fused converts (hi only): hs 4096 blocks, wq/wk/wv/wo 1024 each
__global__ void cvt_all(const float4* __restrict__ hs,
                        const float4* __restrict__ wq, const float4* __restrict__ wk,
                        const float4* __restrict__ wv, const float4* __restrict__ wo) {
    int bid = blockIdx.x, tid = threadIdx.x;
    if (bid < 4096)        cvt4hi(hs, (uint2*)d_hsh, bid*256 + tid);
    else if (bid < 5120)   cvt4hi(wq, (uint2*)d_wqh, (bid-4096)*256 + tid);
    else if (bid < 6144)   cvt4hi(wk, (uint2*)d_wkh, (bid-5120)*256 + tid);
    else if (bid < 7168)   cvt4hi(wv, (uint2*)d_wvh, (bid-6144)*256 + tid);
    else                   cvt4hi(wo, (uint2*)d_woh, (bid-7168)*256 + tid);
}

__global__ void cvt_T_k(const float* __restrict__ src) {
    int idx = blockIdx.x * blockDim.x + threadIdx.x;
    if (idx >= DD*DD) return;
    int k = idx & (DD-1), n = idx >> 10;
    d_memTh[(size_t)n*DD + k] = __float2half_rn(src[(size_t)k*DD + n]);
}

__global__ void normq_kernel(const float* __restrict__ mnorm) {
    int warp = (blockIdx.x * blockDim.x + threadIdx.x) >> 5;
    int lane = threadIdx.x & 31;
    if (warp >= MTOT) return;
    const float* row = d_sq + (size_t)warp * DD;
    float s = 0.f;
    for (int k = lane; k < DD; k += 32) s += row[k] * mnorm[k];
    #pragma unroll
    for (int o = 16; o > 0; o >>= 1) s += __shfl_xor_sync(0xffffffffu, s, o);
    if (lane == 0) d_normq[warp] = fmaxf(s, EPSV);
}

__global__ void zc_kernel() {
    int idx = blockIdx.x * blockDim.x + threadIdx.x;
    if (idx >= BSZ*NCH*DD) return;
    int d = idx % DD; int bn = idx / DD;
    int b = bn >> 4, n = bn & 15;
    const float* base = d_sk + (size_t)(b*SEQ + n*CH)*DD + d;
    float s = 0.f;
    #pragma unroll 4
    for (int i = 0; i < CH; ++i) s += base[(size_t)i*DD];
    d_zz[idx] = s;
}

__global__ void zprefix_kernel() {
    int idx = blockIdx.x * blockDim.x + threadIdx.x;
    if (idx >= BSZ*DD) return;
    int b = idx / DD, d = idx % DD;
    float run = 0.f;
    for (int n = 0; n < NCH; ++n) {
        float* p = d_zz + (size_t)(b*NCH + n)*DD + d;
        float t = *p; *p = run; run += t;
    }
}

// ---------------- tensor-core GEMM core (pure fp16, single pass) ----------------
#define NT_STRIDE 40
#define T_STRIDE 136
#define MAT_B 10240
#define STAGE_B (2*MAT_B)     // A + B
#define SMEM_TOT (2*STAGE_B)  // 40960

__device__ __forceinline__ void cpa16(void* dst, const void* src) {
    uint32_t d = (uint32_t)__cvta_generic_to_shared(dst);
    asm volatile("cp.async.cg.shared.global [%0], [%1], 16;" :: "r"(d), "l"(src));
}
__device__ __forceinline__ void cp_commit() { asm volatile("cp.async.commit_group;"); }
__device__ __forceinline__ void cp_wait1()  { asm volatile("cp.async.wait_group 1;"); }

__device__ __forceinline__ void ldsm4a(uint32_t* r, uint32_t a) {
    asm volatile("ldmatrix.sync.aligned.m8n8.x4.shared.b16 {%0,%1,%2,%3}, [%4];"
        : "=r"(r[0]), "=r"(r[1]), "=r"(r[2]), "=r"(r[3]) : "r"(a));
}
__device__ __forceinline__ void ldsm4ta(uint32_t* r, uint32_t a) {
    asm volatile("ldmatrix.sync.aligned.m8n8.x4.trans.shared.b16 {%0,%1,%2,%3}, [%4];"
        : "=r"(r[0]), "=r"(r[1]), "=r"(r[2]), "=r"(r[3]) : "r"(a));
}
__device__ __forceinline__ void mma_f16(float* c, const uint32_t* a, const uint32_t* b) {
    asm volatile("mma.sync.aligned.m16n8k16.row.col.f32.f16.f16.f32 "
        "{%0,%1,%2,%3}, {%4,%5,%6,%7}, {%8,%9}, {%0,%1,%2,%3};"
        : "+f"(c[0]), "+f"(c[1]), "+f"(c[2]), "+f"(c[3])
        : "r"(a[0]), "r"(a[1]), "r"(a[2]), "r"(a[3]), "r"(b[0]), "r"(b[1]));
}

struct Op { const hf* p; int ld; };

template<int TA, int TB>
__device__ __forceinline__ void stage(Op A, Op B, int k0, char* sm, int tid) {
    hf* Ah = (hf*)sm;
    hf* Bh = (hf*)(sm + MAT_B);
    #pragma unroll
    for (int i = 0; i < 2; ++i) {
        int idx = tid + 256*i;
        if (!TA) {
            int row = idx >> 2, ch = idx & 3;
            cpa16(Ah + row*NT_STRIDE + ch*8, A.p + (size_t)row*A.ld + k0 + ch*8);
        } else {
            int row = idx >> 4, ch = idx & 15;
            cpa16(Ah + row*T_STRIDE + ch*8, A.p + (size_t)(k0 + row)*A.ld + ch*8);
        }
        if (!TB) {
            int row = idx >> 2, ch = idx & 3;
            cpa16(Bh + row*NT_STRIDE + ch*8, B.p + (size_t)row*B.ld + k0 + ch*8);
        } else {
            int row = idx >> 4, ch = idx & 15;
            cpa16(Bh + row*T_STRIDE + ch*8, B.p + (size_t)(k0 + row)*B.ld + ch*8);
        }
    }
}

struct LaneOff {
    uint32_t a[2];
    uint32_t b[4];
};
template<int TA, int TB>
__device__ __forceinline__ LaneOff make_off(int lane, int wm, int wn) {
    LaneOff lo;
    #pragma unroll
    for (int mt = 0; mt < 2; ++mt) {
        lo.a[mt] = (!TA)
            ? (uint32_t)(((wm + mt*16 + (lane & 15))*NT_STRIDE + ((lane >> 4) << 3)) * 2)
            : (uint32_t)(((((lane >> 4) << 3) + (lane & 7))*T_STRIDE + wm + mt*16 + (lane & 8)) * 2);
    }
    #pragma unroll
    for (int nq = 0; nq < 4; ++nq) {
        lo.b[nq] = (!TB)
            ? (uint32_t)(MAT_B + ((wn + nq*16 + (lane & 15))*NT_STRIDE + ((lane >> 4) << 3)) * 2)
            : (uint32_t)(MAT_B + (((lane & 15))*T_STRIDE + wn + nq*16 + ((lane >> 4) << 3)) * 2);
    }
    return lo;
}

template<int TA, int TB>
__device__ __forceinline__ void compute16(uint32_t smaddr, int ks, const LaneOff& lo,
                                          float acc[2][8][4]) {
    const uint32_t dA = (!TA) ? (uint32_t)(2*ks) : (uint32_t)(2*ks*T_STRIDE);
    const uint32_t dB = (!TB) ? (uint32_t)(2*ks) : (uint32_t)(2*ks*T_STRIDE);
    uint32_t ah[2][4], bh[8][2];
    #pragma unroll
    for (int mt = 0; mt < 2; ++mt) {
        uint32_t a = smaddr + lo.a[mt] + dA;
        if (!TA) ldsm4a(ah[mt], a); else ldsm4ta(ah[mt], a);
    }
    #pragma unroll
    for (int nq = 0; nq < 4; ++nq) {
        uint32_t a = smaddr + lo.b[nq] + dB;
        uint32_t r[4];
        if (!TB) {
            ldsm4a(r, a);
            bh[2*nq][0]=r[0]; bh[2*nq][1]=r[2]; bh[2*nq+1][0]=r[1]; bh[2*nq+1][1]=r[3];
        } else {
            ldsm4ta(r, a);
            bh[2*nq][0]=r[0]; bh[2*nq][1]=r[1]; bh[2*nq+1][0]=r[2]; bh[2*nq+1][1]=r[3];
        }
    }
    #pragma unroll
    for (int mt = 0; mt < 2; ++mt)
        #pragma unroll
        for (int nt = 0; nt < 8; ++nt)
            mma_f16(acc[mt][nt], ah[mt], bh[nt]);
}

template<int TA, int TB>
__device__ __forceinline__ void gemm_core(Op A, Op B, int K, float acc[2][8][4],
                                          char* smbase, int tid) {
    const int lane = tid & 31, wid = tid >> 5;
    const int wm = (wid & 3) * 32, wn = (wid >> 2) * 64;
    const LaneOff lo = make_off<TA,TB>(lane, wm, wn);
    const uint32_t base0 = (uint32_t)__cvta_generic_to_shared(smbase);
    const int KT = K >> 5;
    stage<TA,TB>(A, B, 0, smbase, tid);
    cp_commit();
    for (int kt = 0; kt < KT; ++kt) {
        if (kt + 1 < KT) stage<TA,TB>(A, B, (kt+1) << 5, smbase + ((kt+1) & 1)*STAGE_B, tid);
        cp_commit();
        cp_wait1();
        __syncthreads();
        uint32_t cur = base0 + (uint32_t)((kt & 1)*STAGE_B);
        compute16<TA,TB>(cur, 0,  lo, acc);
        compute16<TA,TB>(cur, 16, lo, acc);
        __syncthreads();
    }
}

#define GEMM_SMEM extern __shared__ char sm_[];

#define EPI_COORDS \
    const int lane = tid & 31, wid = tid >> 5; \
    const int gid = lane >> 2, tig = lane & 3; \
    const int wm = (wid & 3) * 32, wn = (wid >> 2) * 64;

#define EPI_LOOP(BODY) \
    _Pragma("unroll") for (int mt = 0; mt < 2; ++mt) \
    _Pragma("unroll") for (int nt = 0; nt < 8; ++nt) \
    _Pragma("unroll") for (int ci = 0; ci < 4; ++ci) { \
        int mr = wm + mt*16 + gid + ((ci >> 1) ? 8 : 0); \
        int nr = wn + nt*8 + tig*2 + (ci & 1); \
        float v = acc[mt][nt][ci]; \
        BODY \
    }

// ---------------- GEMM kernels ----------------
__global__ void __launch_bounds__(256, 2) tc_proj3() {
    GEMM_SMEM;
    int tid = threadIdx.x;
    int m0 = blockIdx.y * 128, n0 = blockIdx.x * 128;
    int which = blockIdx.z;
    const hf* wh = (which==0) ? d_wqh : (which==1) ? d_wkh : d_wvh;
    float acc[2][8][4] = {};
    Op A{d_hsh + (size_t)m0*DD, DD};
    Op B{wh + (size_t)n0*DD, DD};
    gemm_core<0,0>(A, B, DD, acc, sm_, tid);
    EPI_COORDS;
    if (which == 0) {
        EPI_LOOP({
            size_t o = (size_t)(m0+mr)*DD + n0 + nr;
            v = (v > 0.f) ? v + 1.f : expf(v);
            d_sq[o] = v; d_sqh[o] = __float2half_rn(v);
        })
    } else if (which == 1) {
        EPI_LOOP({
            size_t o = (size_t)(m0+mr)*DD + n0 + nr;
            v = (v > 0.f) ? v + 1.f : expf(v);
            d_sk[o] = v; d_skh[o] = __float2half_rn(v);
        })
    } else {
        EPI_LOOP({
            size_t o = (size_t)(m0+mr)*DD + n0 + nr;
            d_vh[o] = __float2half_rn(v);
        })
    }
}

// fused wave2: memout (256 blocks) + kv (2048) + scores (32)
__global__ void __launch_bounds__(256, 2) wave2() {
    GEMM_SMEM;
    int tid = threadIdx.x;
    int bid = blockIdx.x;
    if (bid < 256) {
        int m0 = (bid >> 3) * 128, n0 = (bid & 7) * 128;
        float acc[2][8][4] = {};
        Op A{d_sqh + (size_t)m0*DD, DD};
        Op B{d_memTh + (size_t)n0*DD, DD};
        gemm_core<0,0>(A, B, DD, acc, sm_, tid);
        float gs = d_scal[0] * d_scal[1];
        EPI_COORDS;
        EPI_LOOP({
            d_memout[(size_t)(m0+mr)*DD + n0 + nr] = v * gs / d_normq[m0+mr];
        })
    } else if (bid < 2304) {
        int idx = bid - 256;
        int bn = idx >> 6, loc = idx & 63;
        int b = bn >> 4, n = bn & 15;
        size_t cb = (size_t)(b*SEQ + n*CH)*DD;
        int m0 = (loc >> 3) * 128, n0 = (loc & 7) * 128;
        float acc[2][8][4] = {};
        Op A{d_skh + cb + m0, DD};
        Op B{d_vh + cb + n0, DD};
        gemm_core<1,1>(A, B, CH, acc, sm_, tid);
        float* C = d_G + (size_t)bn*DD*DD;
        EPI_COORDS;
        EPI_LOOP({
            C[(size_t)(m0+mr)*DD + n0 + nr] = v;
        })
    } else {
        int bn = bid - 2304;
        int b = bn >> 4, n = bn & 15;
        size_t cb = (size_t)(b*SEQ + n*CH)*DD;
        float acc[2][8][4] = {};
        Op A{d_sqh + cb, DD};
        Op B{d_skh + cb, DD};
        gemm_core<0,0>(A, B, DD, acc, sm_, tid);
        size_t co = (size_t)bn*CH*CH;
        EPI_COORDS;
        EPI_LOOP({
            float m = (nr <= mr) ? v : 0.f;
            size_t o = co + (size_t)mr*CH + nr;
            d_Abuf[o] = m;
            d_Abh[o] = __float2half_rn(m);
        })
    }
}

// fused wave3: gprefix (8192 blocks) + den (512 blocks)
__global__ void __launch_bounds__(256) wave3() {
    int bid = blockIdx.x, tid = threadIdx.x;
    if (bid < 8192) {
        size_t idx = (size_t)bid*256 + tid;
        int b = (int)(idx / ((size_t)DD*DD));
        size_t rem = idx % ((size_t)DD*DD);
        float run = 0.f;
        for (int n = 0; n < NCH; ++n) {
            size_t off = ((size_t)(b*NCH + n)*DD*DD) + rem;
            float t = d_G[off];
            d_Sph[off] = __float2half_rn(run);
            run += t;
        }
    } else {
        int warp = ((bid - 8192)*256 + tid) >> 5;
        int lane = tid & 31;
        if (warp >= BSZ*NCH*CH) return;
        int bn = warp / CH, i = warp % CH;
        int b = bn >> 4, n = bn & 15;
        const float* qr = d_sq + (size_t)(b*SEQ + n*CH + i)*DD;
        const float* zr = d_zz + (size_t)bn*DD;
        float s = 0.f;
        for (int k = lane; k < DD; k += 32) s += qr[k] * zr[k];
        const float* ar = d_Abuf + (size_t)bn*CH*CH + (size_t)i*CH;
        for (int j = lane; j < CH; j += 32) s += ar[j];
        #pragma unroll
        for (int o = 16; o > 0; o >>= 1) s += __shfl_xor_sync(0xffffffffu, s, o);
        if (lane == 0) d_den[warp] = fmaxf(s, EPSV);
    }
}

// attn: local = (sq @ Sp + Abuf @ v)/den; epilogue fuses combine -> d_cmh
__global__ void __launch_bounds__(256, 2) tc_attn() {
    GEMM_SMEM;
    int tid = threadIdx.x;
    int bn = blockIdx.z; int b = bn >> 4, n = bn & 15;
    size_t cb = (size_t)(b*SEQ + n*CH)*DD;
    int n0 = blockIdx.x * 128;
    float acc[2][8][4] = {};
    {
        Op A{d_sqh + cb, DD};
        Op B{d_Sph + (size_t)bn*DD*DD + n0, DD};   // trans [d][e]
        gemm_core<0,1>(A, B, DD, acc, sm_, tid);
    }
    {
        Op A{d_Abh + (size_t)bn*CH*CH, CH};
        Op B{d_vh + cb + n0, DD};                  // trans [c][e]
        gemm_core<0,1>(A, B, CH, acc, sm_, tid);
    }
    float og = 1.f - d_scal[0];
    EPI_COORDS;
    EPI_LOOP({
        size_t o = cb + (size_t)mr*DD + n0 + nr;
        float cm = d_memout[o] + og * v / d_den[bn*CH + mr];
        d_cmh[o] = __float2half_rn(cm);
    })
}

__global__ void __launch_bounds__(256, 2) tc_final(float* __restrict__ Out) {
    GEMM_SMEM;
    int tid = threadIdx.x;
    int m0 = blockIdx.y * 128, n0 = blockIdx.x * 128;
    float acc[2][8][4] = {};
    Op A{d_cmh + (size_t)m0*DD, DD};
    Op B{d_woh + (size_t)n0*DD, DD};
    gemm_core<0,0>(A, B, DD, acc, sm_, tid);
    EPI_COORDS;
    EPI_LOOP({
        Out[(size_t)(m0+mr)*DD + n0 + nr] = v;
    })
}

// ---------------- launcher ----------------
extern "C" void kernel_launch(void* const* d_in, const int* in_sizes, int n_in,
                              void* d_out, int out_size) {
    const float* hs    = (const float*)d_in[0];
    const float* wq    = (const float*)d_in[1];
    const float* wk    = (const float*)d_in[2];
    const float* wv    = (const float*)d_in[3];
    const float* wo    = (const float*)d_in[4];
    const float* gate  = (const float*)d_in[5];
    const float* mem   = (const float*)d_in[6];
    const float* mnorm = (const float*)d_in[7];
    float* out = (float*)d_out;

    cudaFuncSetAttribute(tc_proj3, cudaFuncAttributeMaxDynamicSharedMemorySize, SMEM_TOT);
    cudaFuncSetAttribute(wave2,    cudaFuncAttributeMaxDynamicSharedMemorySize, SMEM_TOT);
    cudaFuncSetAttribute(tc_attn,  cudaFuncAttributeMaxDynamicSharedMemorySize, SMEM_TOT);
    cudaFuncSetAttribute(tc_final, cudaFuncAttributeMaxDynamicSharedMemorySize, SMEM_TOT);

    scalars_kernel<<<1, 1024>>>(gate, mnorm);

    cvt_all<<<8192, 256>>>((const float4*)hs, (const float4*)wq, (const float4*)wk,
                           (const float4*)wv, (const float4*)wo);
    cvt_T_k<<<(DD*DD+255)/256, 256>>>(mem);

    dim3 gP(DD/128, MTOT/128, 3);       // (8, 32, 3)
    tc_proj3<<<gP, 256, SMEM_TOT>>>();

    normq_kernel<<<(MTOT*32 + 255)/256, 256>>>(mnorm);
    zc_kernel<<<(BSZ*NCH*DD + 255)/256, 256>>>();
    zprefix_kernel<<<(BSZ*DD + 255)/256, 256>>>();

    wave2<<<2336, 256, SMEM_TOT>>>();
    wave3<<<8704, 256>>>();

    dim3 gAt(DD/128, 1, BSZ*NCH);       // (8, 1, 32)
    tc_attn<<<gAt, 256, SMEM_TOT>>>();

    dim3 gM(DD/128, MTOT/128);          // (8, 32)
    tc_final<<<gM, 256, SMEM_TOT>>>(out);
}